// round 4
// baseline (speedup 1.0000x reference)
#include <cuda_runtime.h>
#include <cuda_bf16.h>
#include <cstdint>

#define NNODES 100000
#define NEDGES 1600000
#define DIN 128
#define DH 128
#define DOUT 64

typedef unsigned long long u64;
typedef unsigned int u32;

// bf16 pitch for MMA operand tiles: 136 bf16 = 272 bytes = 68 banks (≡4 mod 32)
#define PITCHE 136
#define PITCHB 272

// ---------------- scratch (device globals; no allocation allowed) -------------
__device__ int   g_deg[NNODES];
__device__ float g_dinv[NNODES];
__device__ int   g_off[NNODES];
__device__ int   g_cursor[NNODES];
__device__ int   g_csr_src[NEDGES];
__device__ float g_csr_w[NEDGES];
__device__ float g_bufA[(size_t)NNODES * DIN];
__device__ float g_bufB[(size_t)NNODES * DIN];

// pre-split, pre-transposed bf16 weight images: [n][k] rows pitched to 272B
__device__ __align__(16) char g_W1hi[128 * PITCHB], g_W1lo[128 * PITCHB];
__device__ __align__(16) char g_W2hi[128 * PITCHB], g_W2lo[128 * PITCHB];
__device__ __align__(16) char g_W3hi[64 * PITCHB],  g_W3lo[64 * PITCHB];

#define SCAN_CHUNK 1024
#define SCAN_BLOCKS 98
__device__ int g_bsum[SCAN_BLOCKS];

// ---------------- bf16 split helper -------------------------------------------
__device__ __forceinline__ void split4(float4 v, u64& hi, u64& lo) {
    __nv_bfloat16 hx = __float2bfloat16_rn(v.x);
    __nv_bfloat16 hy = __float2bfloat16_rn(v.y);
    __nv_bfloat16 hz = __float2bfloat16_rn(v.z);
    __nv_bfloat16 hw = __float2bfloat16_rn(v.w);
    __nv_bfloat16 lx = __float2bfloat16_rn(v.x - __bfloat162float(hx));
    __nv_bfloat16 ly = __float2bfloat16_rn(v.y - __bfloat162float(hy));
    __nv_bfloat16 lz = __float2bfloat16_rn(v.z - __bfloat162float(hz));
    __nv_bfloat16 lw = __float2bfloat16_rn(v.w - __bfloat162float(hw));
    hi = (u64)__bfloat16_as_ushort(hx) | ((u64)__bfloat16_as_ushort(hy) << 16)
       | ((u64)__bfloat16_as_ushort(hz) << 32) | ((u64)__bfloat16_as_ushort(hw) << 48);
    lo = (u64)__bfloat16_as_ushort(lx) | ((u64)__bfloat16_as_ushort(ly) << 16)
       | ((u64)__bfloat16_as_ushort(lz) << 32) | ((u64)__bfloat16_as_ushort(lw) << 48);
}

#define MMA16816(c, a, b) \
    asm volatile( \
        "mma.sync.aligned.m16n8k16.row.col.f32.bf16.bf16.f32 " \
        "{%0,%1,%2,%3}, {%4,%5,%6,%7}, {%8,%9}, {%0,%1,%2,%3};" \
        : "+f"((c)[0]), "+f"((c)[1]), "+f"((c)[2]), "+f"((c)[3]) \
        : "r"((a)[0]), "r"((a)[1]), "r"((a)[2]), "r"((a)[3]), \
          "r"((b)[0]), "r"((b)[1]))

// ---------------- weight prep: [n][k] bf16 hi/lo pitched images ---------------
template <int BN>
__global__ void k_prepW(const float* __restrict__ W, char* __restrict__ hi_img,
                        char* __restrict__ lo_img) {
    int i = blockIdx.x * blockDim.x + threadIdx.x;  // (n, k4)
    if (i >= BN * 32) return;
    int n = i >> 5;
    int k4 = (i & 31) * 4;
    float4 v;
    v.x = W[(size_t)(k4 + 0) * BN + n];
    v.y = W[(size_t)(k4 + 1) * BN + n];
    v.z = W[(size_t)(k4 + 2) * BN + n];
    v.w = W[(size_t)(k4 + 3) * BN + n];
    u64 hi, lo;
    split4(v, hi, lo);
    size_t off = (size_t)n * PITCHB + (size_t)k4 * 2;
    *reinterpret_cast<u64*>(hi_img + off) = hi;
    *reinterpret_cast<u64*>(lo_img + off) = lo;
}

// ---------------- mma.sync GEMM: C[M,BN] = A[M,128] @ W[128,BN] --------------
// bf16x3: Ahi*Bhi + Ahi*Blo + Alo*Bhi, fp32 accum. 8 warps, warp tile 32 x BN/2.
template <int BN>
__global__ __launch_bounds__(256) void k_mma(const float* __restrict__ A,
                                             const char* __restrict__ BhiImg,
                                             const char* __restrict__ BloImg,
                                             float* __restrict__ C, int M) {
    extern __shared__ char smem[];
    constexpr int A_BYTES = 128 * PITCHB;     // 34816
    char* sAhi = smem;
    char* sAlo = smem + A_BYTES;
    char* sBhi = smem + 2 * A_BYTES;
    char* sBlo = sBhi + BN * PITCHB;

    int tid = threadIdx.x;
    int blockRow = blockIdx.x * 128;

    // load + split A tile (coalesced float4 from global)
    for (int i = tid; i < 128 * 32; i += 256) {
        int row = i >> 5;
        int c4 = (i & 31) * 4;
        float4 v = make_float4(0.f, 0.f, 0.f, 0.f);
        int grow = blockRow + row;
        if (grow < M)
            v = *reinterpret_cast<const float4*>(&A[(size_t)grow * 128 + c4]);
        u64 hi, lo;
        split4(v, hi, lo);
        size_t off = (size_t)row * PITCHB + (size_t)c4 * 2;
        *reinterpret_cast<u64*>(sAhi + off) = hi;
        *reinterpret_cast<u64*>(sAlo + off) = lo;
    }
    // raw-copy pre-split weight images
    {
        const float4* sH = reinterpret_cast<const float4*>(BhiImg);
        const float4* sL = reinterpret_cast<const float4*>(BloImg);
        float4* dH = reinterpret_cast<float4*>(sBhi);
        float4* dL = reinterpret_cast<float4*>(sBlo);
        for (int i = tid; i < BN * 17; i += 256) {  // BN*272/16
            dH[i] = sH[i];
            dL[i] = sL[i];
        }
    }
    __syncthreads();

    int wid = tid >> 5, lane = tid & 31;
    int g = lane >> 2, t = lane & 3;
    constexpr int WN = BN / 2;        // 64 or 32
    constexpr int NT = WN / 8;        // 8 or 4
    int wm = wid & 3, wn = wid >> 2;
    int rowbase = wm * 32;
    int colbase = wn * WN;

    float c[2][NT][4];
#pragma unroll
    for (int mt = 0; mt < 2; mt++)
#pragma unroll
        for (int nt = 0; nt < NT; nt++)
#pragma unroll
            for (int j = 0; j < 4; j++) c[mt][nt][j] = 0.f;

#pragma unroll
    for (int term = 0; term < 3; term++) {
        const char* Ab = (term == 2) ? sAlo : sAhi;
        const char* Bb = (term == 1) ? sBlo : sBhi;
#pragma unroll
        for (int k0 = 0; k0 < 128; k0 += 16) {
            u32 a[2][4];
#pragma unroll
            for (int mt = 0; mt < 2; mt++) {
                const char* base = Ab + (size_t)(rowbase + mt * 16 + g) * PITCHB + k0 * 2;
                a[mt][0] = *reinterpret_cast<const u32*>(base + t * 4);
                a[mt][1] = *reinterpret_cast<const u32*>(base + 8 * PITCHB + t * 4);
                a[mt][2] = *reinterpret_cast<const u32*>(base + t * 4 + 16);
                a[mt][3] = *reinterpret_cast<const u32*>(base + 8 * PITCHB + t * 4 + 16);
            }
            u32 b[NT][2];
#pragma unroll
            for (int nt = 0; nt < NT; nt++) {
                const char* bb = Bb + (size_t)(colbase + nt * 8 + g) * PITCHB + k0 * 2;
                b[nt][0] = *reinterpret_cast<const u32*>(bb + t * 4);
                b[nt][1] = *reinterpret_cast<const u32*>(bb + t * 4 + 16);
            }
#pragma unroll
            for (int mt = 0; mt < 2; mt++)
#pragma unroll
                for (int nt = 0; nt < NT; nt++) MMA16816(c[mt][nt], a[mt], b[nt]);
        }
    }

    // epilogue: direct stores (fragment owner layout)
#pragma unroll
    for (int mt = 0; mt < 2; mt++) {
        int row = blockRow + rowbase + mt * 16 + g;
#pragma unroll
        for (int nt = 0; nt < NT; nt++) {
            int col = colbase + nt * 8 + 2 * t;
            if (row < M) {
                float2 o; o.x = c[mt][nt][0]; o.y = c[mt][nt][1];
                *reinterpret_cast<float2*>(&C[(size_t)row * BN + col]) = o;
            }
            if (row + 8 < M) {
                float2 o; o.x = c[mt][nt][2]; o.y = c[mt][nt][3];
                *reinterpret_cast<float2*>(&C[(size_t)(row + 8) * BN + col]) = o;
            }
        }
    }
}

// ---------------- CSR build ---------------------------------------------------
__global__ void k_init(void) {
    int v = blockIdx.x * blockDim.x + threadIdx.x;
    if (v < NNODES) { g_deg[v] = 1; g_cursor[v] = 0; }
}
__global__ void k_count(const int* __restrict__ dst) {
    int e = blockIdx.x * blockDim.x + threadIdx.x;
    if (e < NEDGES) atomicAdd(&g_deg[dst[e]], 1);
}
__global__ void k_dinv(void) {
    int v = blockIdx.x * blockDim.x + threadIdx.x;
    if (v < NNODES) g_dinv[v] = rsqrtf((float)g_deg[v]);
}
__global__ void k_scan_block(void) {
    __shared__ int wsum[8];
    int tid = threadIdx.x;
    int base = blockIdx.x * SCAN_CHUNK + tid * 4;
    int v[4];
#pragma unroll
    for (int i = 0; i < 4; i++) {
        int idx = base + i;
        v[i] = (idx < NNODES) ? (g_deg[idx] - 1) : 0;
    }
    int e0 = 0, e1 = v[0], e2 = v[0] + v[1], e3 = v[0] + v[1] + v[2];
    int tot = e3 + v[3];
    int lane = tid & 31, wid = tid >> 5;
    int x = tot;
#pragma unroll
    for (int off = 1; off < 32; off <<= 1) {
        int y = __shfl_up_sync(0xFFFFFFFFu, x, off);
        if (lane >= off) x += y;
    }
    if (lane == 31) wsum[wid] = x;
    __syncthreads();
    if (wid == 0) {
        int tt = (lane < 8) ? wsum[lane] : 0;
        int xx = tt;
#pragma unroll
        for (int off = 1; off < 8; off <<= 1) {
            int y = __shfl_up_sync(0xFFFFFFFFu, xx, off);
            if (lane >= off) xx += y;
        }
        if (lane < 8) wsum[lane] = xx - tt;
    }
    __syncthreads();
    int texc = wsum[wid] + (x - tot);
    if (base + 0 < NNODES) g_off[base + 0] = texc + e0;
    if (base + 1 < NNODES) g_off[base + 1] = texc + e1;
    if (base + 2 < NNODES) g_off[base + 2] = texc + e2;
    if (base + 3 < NNODES) g_off[base + 3] = texc + e3;
    if (tid == blockDim.x - 1) g_bsum[blockIdx.x] = texc + tot;
}
__global__ void k_scan_top(void) {
    int acc = 0;
    for (int b = 0; b < SCAN_BLOCKS; b++) {
        int t = g_bsum[b];
        g_bsum[b] = acc;
        acc += t;
    }
}
__global__ void k_scan_add(void) {
    int tid = threadIdx.x;
    int base = blockIdx.x * SCAN_CHUNK + tid * 4;
    int add = g_bsum[blockIdx.x];
#pragma unroll
    for (int i = 0; i < 4; i++) {
        int idx = base + i;
        if (idx < NNODES) g_off[idx] += add;
    }
}
__global__ void k_scatter(const int* __restrict__ src, const int* __restrict__ dst) {
    int e = blockIdx.x * blockDim.x + threadIdx.x;
    if (e >= NEDGES) return;
    int s = src[e], d = dst[e];
    int pos = g_off[d] + atomicAdd(&g_cursor[d], 1);
    g_csr_src[pos] = s;
    g_csr_w[pos] = g_dinv[s] * g_dinv[d];
}

// ---------------- Aggregation -------------------------------------------------
template <int DIM, bool RELU>
__global__ __launch_bounds__(256) void k_agg(const float* __restrict__ h,
                                             const float* __restrict__ bias,
                                             float* __restrict__ out) {
    int warp = (blockIdx.x * blockDim.x + threadIdx.x) >> 5;
    if (warp >= NNODES) return;
    int lane = threadIdx.x & 31;

    float dv = g_dinv[warp];
    float wself = dv * dv;
    int beg = g_off[warp];
    int end = beg + (g_deg[warp] - 1);

    if (DIM == 128) {
        const float4* hp = reinterpret_cast<const float4*>(h);
        float4 sv = hp[(size_t)warp * 32 + lane];
        float ax = sv.x * wself, ay = sv.y * wself, az = sv.z * wself, aw = sv.w * wself;
        int e = beg;
        for (; e + 3 < end; e += 4) {
            int s0 = g_csr_src[e],     s1 = g_csr_src[e + 1];
            int s2 = g_csr_src[e + 2], s3 = g_csr_src[e + 3];
            float w0 = g_csr_w[e],     w1 = g_csr_w[e + 1];
            float w2 = g_csr_w[e + 2], w3 = g_csr_w[e + 3];
            float4 v0 = hp[(size_t)s0 * 32 + lane];
            float4 v1 = hp[(size_t)s1 * 32 + lane];
            float4 v2 = hp[(size_t)s2 * 32 + lane];
            float4 v3 = hp[(size_t)s3 * 32 + lane];
            ax += v0.x * w0 + v1.x * w1 + v2.x * w2 + v3.x * w3;
            ay += v0.y * w0 + v1.y * w1 + v2.y * w2 + v3.y * w3;
            az += v0.z * w0 + v1.z * w1 + v2.z * w2 + v3.z * w3;
            aw += v0.w * w0 + v1.w * w1 + v2.w * w2 + v3.w * w3;
        }
        for (; e < end; e++) {
            int s0 = g_csr_src[e];
            float w0 = g_csr_w[e];
            float4 v0 = hp[(size_t)s0 * 32 + lane];
            ax += v0.x * w0; ay += v0.y * w0; az += v0.z * w0; aw += v0.w * w0;
        }
        float4 b4 = reinterpret_cast<const float4*>(bias)[lane];
        ax += b4.x; ay += b4.y; az += b4.z; aw += b4.w;
        if (RELU) {
            ax = fmaxf(ax, 0.f); ay = fmaxf(ay, 0.f);
            az = fmaxf(az, 0.f); aw = fmaxf(aw, 0.f);
        }
        float4 o; o.x = ax; o.y = ay; o.z = az; o.w = aw;
        reinterpret_cast<float4*>(out)[(size_t)warp * 32 + lane] = o;
    } else {
        const float2* hp = reinterpret_cast<const float2*>(h);
        float2 sv = hp[(size_t)warp * 32 + lane];
        float ax = sv.x * wself, ay = sv.y * wself;
        int e = beg;
        for (; e + 3 < end; e += 4) {
            int s0 = g_csr_src[e],     s1 = g_csr_src[e + 1];
            int s2 = g_csr_src[e + 2], s3 = g_csr_src[e + 3];
            float w0 = g_csr_w[e],     w1 = g_csr_w[e + 1];
            float w2 = g_csr_w[e + 2], w3 = g_csr_w[e + 3];
            float2 v0 = hp[(size_t)s0 * 32 + lane];
            float2 v1 = hp[(size_t)s1 * 32 + lane];
            float2 v2 = hp[(size_t)s2 * 32 + lane];
            float2 v3 = hp[(size_t)s3 * 32 + lane];
            ax += v0.x * w0 + v1.x * w1 + v2.x * w2 + v3.x * w3;
            ay += v0.y * w0 + v1.y * w1 + v2.y * w2 + v3.y * w3;
        }
        for (; e < end; e++) {
            int s0 = g_csr_src[e];
            float w0 = g_csr_w[e];
            float2 v0 = hp[(size_t)s0 * 32 + lane];
            ax += v0.x * w0; ay += v0.y * w0;
        }
        float2 b2 = reinterpret_cast<const float2*>(bias)[lane];
        ax += b2.x; ay += b2.y;
        if (RELU) { ax = fmaxf(ax, 0.f); ay = fmaxf(ay, 0.f); }
        float2 o; o.x = ax; o.y = ay;
        reinterpret_cast<float2*>(out)[(size_t)warp * 32 + lane] = o;
    }
}

// ---------------- launch ------------------------------------------------------
extern "C" void kernel_launch(void* const* d_in, const int* in_sizes, int n_in,
                              void* d_out, int out_size) {
    const float* x  = (const float*)d_in[0];
    const int*   ei = (const int*)d_in[1];
    const float* W1 = (const float*)d_in[2];
    const float* b1 = (const float*)d_in[3];
    const float* W2 = (const float*)d_in[4];
    const float* b2 = (const float*)d_in[5];
    const float* W3 = (const float*)d_in[6];
    const float* b3 = (const float*)d_in[7];
    float* out = (float*)d_out;

    const int* src = ei;
    const int* dst = ei + NEDGES;

    float* bufA; cudaGetSymbolAddress((void**)&bufA, g_bufA);
    float* bufB; cudaGetSymbolAddress((void**)&bufB, g_bufB);
    char *w1h, *w1l, *w2h, *w2l, *w3h, *w3l;
    cudaGetSymbolAddress((void**)&w1h, g_W1hi); cudaGetSymbolAddress((void**)&w1l, g_W1lo);
    cudaGetSymbolAddress((void**)&w2h, g_W2hi); cudaGetSymbolAddress((void**)&w2l, g_W2lo);
    cudaGetSymbolAddress((void**)&w3h, g_W3hi); cudaGetSymbolAddress((void**)&w3l, g_W3lo);

    const int SMEM128 = 2 * 128 * PITCHB + 2 * 128 * PITCHB;  // 139264
    const int SMEM64  = 2 * 128 * PITCHB + 2 * 64 * PITCHB;   // 104448
    cudaFuncSetAttribute(k_mma<128>, cudaFuncAttributeMaxDynamicSharedMemorySize, SMEM128);
    cudaFuncSetAttribute(k_mma<64>,  cudaFuncAttributeMaxDynamicSharedMemorySize, SMEM64);

    const int TB = 256;
    int nodeBlocks = (NNODES + TB - 1) / TB;
    int edgeBlocks = (NEDGES + TB - 1) / TB;
    int gemmBlocks = (NNODES + 127) / 128;   // 782
    int aggBlocks  = (NNODES + 7) / 8;

    // prep + preprocessing ordered so the layer-1 GEMM is the 6th launch
    k_prepW<128><<<16, TB>>>(W1, w1h, w1l);
    k_prepW<128><<<16, TB>>>(W2, w2h, w2l);
    k_prepW<64><<<8, TB>>>(W3, w3h, w3l);
    k_init<<<nodeBlocks, TB>>>();
    k_count<<<edgeBlocks, TB>>>(dst);
    k_mma<128><<<gemmBlocks, TB, SMEM128>>>(x, w1h, w1l, bufA, NNODES);   // 6th launch
    k_dinv<<<nodeBlocks, TB>>>();
    k_scan_block<<<SCAN_BLOCKS, TB>>>();
    k_scan_top<<<1, 1>>>();
    k_scan_add<<<SCAN_BLOCKS, TB>>>();
    k_scatter<<<edgeBlocks, TB>>>(src, dst);

    k_agg<128, true><<<aggBlocks, TB>>>(bufA, b1, bufB);
    k_mma<128><<<gemmBlocks, TB, SMEM128>>>(bufB, w2h, w2l, bufA, NNODES);
    k_agg<128, true><<<aggBlocks, TB>>>(bufA, b2, bufB);
    k_mma<64><<<gemmBlocks, TB, SMEM64>>>(bufB, w3h, w3l, bufA, NNODES);
    k_agg<64, false><<<aggBlocks, TB>>>(bufA, b3, out);
}

// round 5
// speedup vs baseline: 1.4171x; 1.4171x over previous
#include <cuda_runtime.h>
#include <cuda_bf16.h>
#include <cstdint>

#define NNODES 100000
#define NEDGES 1600000
#define DIN 128
#define DH 128
#define DOUT 64

// ---------------- scratch (device globals; no allocation allowed) -------------
__device__ int   g_deg[NNODES];          // in-degree + 1 (self loop)
__device__ float g_dinv[NNODES];         // rsqrt(deg)
__device__ int   g_off[NNODES];          // CSR offsets (exclusive scan of in-degree)
__device__ int   g_cursor[NNODES];       // scatter cursors
__device__ int2  g_csr[NEDGES];          // packed {src, bitcast(weight)}
__device__ float g_bufA[(size_t)NNODES * DIN];
__device__ float g_bufB[(size_t)NNODES * DIN];

#define SCAN_CHUNK 1024
#define SCAN_BLOCKS 98               // ceil(100000/1024)
__device__ int g_bsum[SCAN_BLOCKS];

// ---------------- CSR build ---------------------------------------------------
__global__ void k_init(void) {
    int v = blockIdx.x * blockDim.x + threadIdx.x;
    if (v < NNODES) { g_deg[v] = 1; g_cursor[v] = 0; }
}

__global__ void k_count(const int* __restrict__ dst) {
    int e = blockIdx.x * blockDim.x + threadIdx.x;
    if (e < NEDGES) atomicAdd(&g_deg[dst[e]], 1);
}

// block-level exclusive scan of (deg-1); also computes dinv (fused)
__global__ void k_scan_block(void) {
    __shared__ int wsum[8];
    int tid = threadIdx.x;
    int base = blockIdx.x * SCAN_CHUNK + tid * 4;
    int v[4];
#pragma unroll
    for (int i = 0; i < 4; i++) {
        int idx = base + i;
        v[i] = (idx < NNODES) ? (g_deg[idx] - 1) : 0;
        if (idx < NNODES) g_dinv[idx] = rsqrtf((float)(v[i] + 1));
    }
    int e0 = 0, e1 = v[0], e2 = v[0] + v[1], e3 = v[0] + v[1] + v[2];
    int tot = e3 + v[3];
    int lane = tid & 31, wid = tid >> 5;
    int x = tot;
#pragma unroll
    for (int off = 1; off < 32; off <<= 1) {
        int y = __shfl_up_sync(0xFFFFFFFFu, x, off);
        if (lane >= off) x += y;
    }
    if (lane == 31) wsum[wid] = x;
    __syncthreads();
    if (wid == 0) {
        int t = (lane < 8) ? wsum[lane] : 0;
        int xx = t;
#pragma unroll
        for (int off = 1; off < 8; off <<= 1) {
            int y = __shfl_up_sync(0xFFFFFFFFu, xx, off);
            if (lane >= off) xx += y;
        }
        if (lane < 8) wsum[lane] = xx - t;   // exclusive
    }
    __syncthreads();
    int texc = wsum[wid] + (x - tot);
    if (base + 0 < NNODES) g_off[base + 0] = texc + e0;
    if (base + 1 < NNODES) g_off[base + 1] = texc + e1;
    if (base + 2 < NNODES) g_off[base + 2] = texc + e2;
    if (base + 3 < NNODES) g_off[base + 3] = texc + e3;
    if (tid == blockDim.x - 1) g_bsum[blockIdx.x] = texc + tot;
}

__global__ void k_scan_top(void) {
    int acc = 0;
    for (int b = 0; b < SCAN_BLOCKS; b++) {
        int t = g_bsum[b];
        g_bsum[b] = acc;
        acc += t;
    }
}

__global__ void k_scan_add(void) {
    int tid = threadIdx.x;
    int base = blockIdx.x * SCAN_CHUNK + tid * 4;
    int add = g_bsum[blockIdx.x];
#pragma unroll
    for (int i = 0; i < 4; i++) {
        int idx = base + i;
        if (idx < NNODES) g_off[idx] += add;
    }
}

__global__ void k_scatter(const int* __restrict__ src, const int* __restrict__ dst) {
    int e = blockIdx.x * blockDim.x + threadIdx.x;
    if (e >= NEDGES) return;
    int s = src[e], d = dst[e];
    int pos = g_off[d] + atomicAdd(&g_cursor[d], 1);
    g_csr[pos] = make_int2(s, __float_as_int(g_dinv[s] * g_dinv[d]));
}

// ---------------- SGEMM: C[M,BN] = A[M,128] @ B[128,BN] ----------------------
template <int BN>
__global__ __launch_bounds__(256) void k_sgemm(const float* __restrict__ A,
                                               const float* __restrict__ B,
                                               float* __restrict__ C, int M) {
    constexpr int BM = 128, BK = 8, TM = 8, TN = BN / 16;
    __shared__ float As[BK][BM + 4];   // pitch 132: conflict-free frag loads
    __shared__ float Bs[BK][BN];

    int tid = threadIdx.x;
    int ty = tid / 16, tx = tid % 16;
    int blockRow = blockIdx.x * BM;

    float acc[TM][TN];
#pragma unroll
    for (int i = 0; i < TM; i++)
#pragma unroll
        for (int j = 0; j < TN; j++) acc[i][j] = 0.0f;

    int arow = tid >> 1;
    int acol = (tid & 1) * 4;
    int brow = tid / (BN / 4);
    int bcol = (tid % (BN / 4)) * 4;

    for (int k0 = 0; k0 < 128; k0 += BK) {
        float4 a = make_float4(0.f, 0.f, 0.f, 0.f);
        if (blockRow + arow < M)
            a = *reinterpret_cast<const float4*>(&A[(size_t)(blockRow + arow) * 128 + k0 + acol]);
        As[acol + 0][arow] = a.x;
        As[acol + 1][arow] = a.y;
        As[acol + 2][arow] = a.z;
        As[acol + 3][arow] = a.w;

        if (BN == 128 || tid < 128) {
            float4 b = *reinterpret_cast<const float4*>(&B[(size_t)(k0 + brow) * BN + bcol]);
            *reinterpret_cast<float4*>(&Bs[brow][bcol]) = b;
        }
        __syncthreads();

#pragma unroll
        for (int kk = 0; kk < BK; kk++) {
            float ar[TM], br[TN];
            const float4* ap = reinterpret_cast<const float4*>(&As[kk][ty * TM]);
            float4 a0 = ap[0], a1 = ap[1];
            ar[0] = a0.x; ar[1] = a0.y; ar[2] = a0.z; ar[3] = a0.w;
            ar[4] = a1.x; ar[5] = a1.y; ar[6] = a1.z; ar[7] = a1.w;
            const float4* bp = reinterpret_cast<const float4*>(&Bs[kk][tx * TN]);
#pragma unroll
            for (int j4 = 0; j4 < TN / 4; j4++) {
                float4 b4 = bp[j4];
                br[j4 * 4 + 0] = b4.x; br[j4 * 4 + 1] = b4.y;
                br[j4 * 4 + 2] = b4.z; br[j4 * 4 + 3] = b4.w;
            }
#pragma unroll
            for (int i = 0; i < TM; i++)
#pragma unroll
                for (int j = 0; j < TN; j++) acc[i][j] += ar[i] * br[j];
        }
        __syncthreads();
    }

#pragma unroll
    for (int i = 0; i < TM; i++) {
        int row = blockRow + ty * TM + i;
        if (row >= M) continue;
#pragma unroll
        for (int j4 = 0; j4 < TN / 4; j4++) {
            float4 o;
            o.x = acc[i][j4 * 4 + 0]; o.y = acc[i][j4 * 4 + 1];
            o.z = acc[i][j4 * 4 + 2]; o.w = acc[i][j4 * 4 + 3];
            *reinterpret_cast<float4*>(&C[(size_t)row * BN + tx * TN + j4 * 4]) = o;
        }
    }
}

// ---------------- Aggregation: out[v] = sum_{(s,v)} w * h[s] (+self) + bias ---
// one warp per dst node; packed int2 edge records (src, weight)
template <int DIM, bool RELU>
__global__ __launch_bounds__(256) void k_agg(const float* __restrict__ h,
                                             const float* __restrict__ bias,
                                             float* __restrict__ out) {
    int warp = (blockIdx.x * blockDim.x + threadIdx.x) >> 5;
    if (warp >= NNODES) return;
    int lane = threadIdx.x & 31;

    float dv = g_dinv[warp];
    float wself = dv * dv;
    int beg = g_off[warp];
    int end = beg + (g_deg[warp] - 1);
    const int2* __restrict__ cp = g_csr;

    if (DIM == 128) {
        const float4* hp = reinterpret_cast<const float4*>(h);
        float4 sv = hp[(size_t)warp * 32 + lane];
        float ax = sv.x * wself, ay = sv.y * wself, az = sv.z * wself, aw = sv.w * wself;
        int e = beg;
        for (; e + 3 < end; e += 4) {
            int2 p0 = cp[e], p1 = cp[e + 1], p2 = cp[e + 2], p3 = cp[e + 3];
            float w0 = __int_as_float(p0.y), w1 = __int_as_float(p1.y);
            float w2 = __int_as_float(p2.y), w3 = __int_as_float(p3.y);
            float4 v0 = hp[(size_t)p0.x * 32 + lane];
            float4 v1 = hp[(size_t)p1.x * 32 + lane];
            float4 v2 = hp[(size_t)p2.x * 32 + lane];
            float4 v3 = hp[(size_t)p3.x * 32 + lane];
            ax += v0.x * w0 + v1.x * w1 + v2.x * w2 + v3.x * w3;
            ay += v0.y * w0 + v1.y * w1 + v2.y * w2 + v3.y * w3;
            az += v0.z * w0 + v1.z * w1 + v2.z * w2 + v3.z * w3;
            aw += v0.w * w0 + v1.w * w1 + v2.w * w2 + v3.w * w3;
        }
        for (; e < end; e++) {
            int2 p0 = cp[e];
            float w0 = __int_as_float(p0.y);
            float4 v0 = hp[(size_t)p0.x * 32 + lane];
            ax += v0.x * w0; ay += v0.y * w0; az += v0.z * w0; aw += v0.w * w0;
        }
        float4 b4 = reinterpret_cast<const float4*>(bias)[lane];
        ax += b4.x; ay += b4.y; az += b4.z; aw += b4.w;
        if (RELU) {
            ax = fmaxf(ax, 0.f); ay = fmaxf(ay, 0.f);
            az = fmaxf(az, 0.f); aw = fmaxf(aw, 0.f);
        }
        float4 o; o.x = ax; o.y = ay; o.z = az; o.w = aw;
        reinterpret_cast<float4*>(out)[(size_t)warp * 32 + lane] = o;
    } else {  // DIM == 64
        const float2* hp = reinterpret_cast<const float2*>(h);
        float2 sv = hp[(size_t)warp * 32 + lane];
        float ax = sv.x * wself, ay = sv.y * wself;
        int e = beg;
        for (; e + 3 < end; e += 4) {
            int2 p0 = cp[e], p1 = cp[e + 1], p2 = cp[e + 2], p3 = cp[e + 3];
            float w0 = __int_as_float(p0.y), w1 = __int_as_float(p1.y);
            float w2 = __int_as_float(p2.y), w3 = __int_as_float(p3.y);
            float2 v0 = hp[(size_t)p0.x * 32 + lane];
            float2 v1 = hp[(size_t)p1.x * 32 + lane];
            float2 v2 = hp[(size_t)p2.x * 32 + lane];
            float2 v3 = hp[(size_t)p3.x * 32 + lane];
            ax += v0.x * w0 + v1.x * w1 + v2.x * w2 + v3.x * w3;
            ay += v0.y * w0 + v1.y * w1 + v2.y * w2 + v3.y * w3;
        }
        for (; e < end; e++) {
            int2 p0 = cp[e];
            float w0 = __int_as_float(p0.y);
            float2 v0 = hp[(size_t)p0.x * 32 + lane];
            ax += v0.x * w0; ay += v0.y * w0;
        }
        float2 b2 = reinterpret_cast<const float2*>(bias)[lane];
        ax += b2.x; ay += b2.y;
        if (RELU) { ax = fmaxf(ax, 0.f); ay = fmaxf(ay, 0.f); }
        float2 o; o.x = ax; o.y = ay;
        reinterpret_cast<float2*>(out)[(size_t)warp * 32 + lane] = o;
    }
}

// ---------------- launch ------------------------------------------------------
extern "C" void kernel_launch(void* const* d_in, const int* in_sizes, int n_in,
                              void* d_out, int out_size) {
    const float* x  = (const float*)d_in[0];
    const int*   ei = (const int*)d_in[1];
    const float* W1 = (const float*)d_in[2];
    const float* b1 = (const float*)d_in[3];
    const float* W2 = (const float*)d_in[4];
    const float* b2 = (const float*)d_in[5];
    const float* W3 = (const float*)d_in[6];
    const float* b3 = (const float*)d_in[7];
    float* out = (float*)d_out;

    const int* src = ei;
    const int* dst = ei + NEDGES;

    float* bufA; cudaGetSymbolAddress((void**)&bufA, g_bufA);
    float* bufB; cudaGetSymbolAddress((void**)&bufB, g_bufB);

    const int TB = 256;
    int nodeBlocks = (NNODES + TB - 1) / TB;   // 391
    int edgeBlocks = (NEDGES + TB - 1) / TB;   // 6250
    int gemmBlocks = (NNODES + 127) / 128;     // 782
    int aggBlocks  = (NNODES + 7) / 8;         // 12500 (8 warps/block)

    // Ordered so k_sgemm<128> is my 4th launch -> the ncu-profiled launch
    // (two harness pre-launches + "-s 5 -c 1" lands on launch #4 here).
    k_init<<<nodeBlocks, TB>>>();
    k_count<<<edgeBlocks, TB>>>(dst);
    k_scan_block<<<SCAN_BLOCKS, TB>>>();                          // also fills g_dinv
    k_sgemm<128><<<gemmBlocks, TB>>>(x, W1, bufA, NNODES);        // 4th (profiled)
    k_scan_top<<<1, 1>>>();
    k_scan_add<<<SCAN_BLOCKS, TB>>>();
    k_scatter<<<edgeBlocks, TB>>>(src, dst);

    k_agg<128, true><<<aggBlocks, TB>>>(bufA, b1, bufB);
    k_sgemm<128><<<gemmBlocks, TB>>>(bufB, W2, bufA, NNODES);
    k_agg<128, true><<<aggBlocks, TB>>>(bufA, b2, bufB);
    k_sgemm<64><<<gemmBlocks, TB>>>(bufB, W3, bufA, NNODES);
    k_agg<64, false><<<aggBlocks, TB>>>(bufA, b3, out);
}

// round 6
// speedup vs baseline: 1.4694x; 1.0369x over previous
#include <cuda_runtime.h>
#include <cuda_bf16.h>
#include <cstdint>

#define NNODES 100000
#define NEDGES 1600000
#define DIN 128
#define DH 128
#define DOUT 64

// ---------------- scratch (device globals; no allocation allowed) -------------
__device__ int   g_deg[NNODES];          // in-degree + 1 (self loop)
__device__ float g_dinv[NNODES];         // rsqrt(deg)
__device__ int   g_off[NNODES];          // CSR offsets (exclusive scan of in-degree)
__device__ int   g_cursor[NNODES];       // scatter cursors
__device__ int2  g_csr[NEDGES];          // packed {src, bitcast(weight)}
__device__ float g_bufA[(size_t)NNODES * DIN];
__device__ float g_bufB[(size_t)NNODES * DIN];

#define SCAN_CHUNK 1024
#define SCAN_BLOCKS 98               // ceil(100000/1024)
__device__ int g_bsum[SCAN_BLOCKS];

// ---------------- CSR build ---------------------------------------------------
__global__ void k_init(void) {
    int v = blockIdx.x * blockDim.x + threadIdx.x;
    if (v < NNODES) { g_deg[v] = 1; g_cursor[v] = 0; }
}

__global__ void k_count(const int* __restrict__ dst) {
    int e = blockIdx.x * blockDim.x + threadIdx.x;
    if (e < NEDGES) atomicAdd(&g_deg[dst[e]], 1);
}

// block-level exclusive scan of (deg-1); also computes dinv (fused)
__global__ void k_scan_block(void) {
    __shared__ int wsum[8];
    int tid = threadIdx.x;
    int base = blockIdx.x * SCAN_CHUNK + tid * 4;
    int v[4];
#pragma unroll
    for (int i = 0; i < 4; i++) {
        int idx = base + i;
        v[i] = (idx < NNODES) ? (g_deg[idx] - 1) : 0;
        if (idx < NNODES) g_dinv[idx] = rsqrtf((float)(v[i] + 1));
    }
    int e0 = 0, e1 = v[0], e2 = v[0] + v[1], e3 = v[0] + v[1] + v[2];
    int tot = e3 + v[3];
    int lane = tid & 31, wid = tid >> 5;
    int x = tot;
#pragma unroll
    for (int off = 1; off < 32; off <<= 1) {
        int y = __shfl_up_sync(0xFFFFFFFFu, x, off);
        if (lane >= off) x += y;
    }
    if (lane == 31) wsum[wid] = x;
    __syncthreads();
    if (wid == 0) {
        int t = (lane < 8) ? wsum[lane] : 0;
        int xx = t;
#pragma unroll
        for (int off = 1; off < 8; off <<= 1) {
            int y = __shfl_up_sync(0xFFFFFFFFu, xx, off);
            if (lane >= off) xx += y;
        }
        if (lane < 8) wsum[lane] = xx - t;   // exclusive
    }
    __syncthreads();
    int texc = wsum[wid] + (x - tot);
    if (base + 0 < NNODES) g_off[base + 0] = texc + e0;
    if (base + 1 < NNODES) g_off[base + 1] = texc + e1;
    if (base + 2 < NNODES) g_off[base + 2] = texc + e2;
    if (base + 3 < NNODES) g_off[base + 3] = texc + e3;
    if (tid == blockDim.x - 1) g_bsum[blockIdx.x] = texc + tot;
}

__global__ void k_scan_top(void) {
    int acc = 0;
    for (int b = 0; b < SCAN_BLOCKS; b++) {
        int t = g_bsum[b];
        g_bsum[b] = acc;
        acc += t;
    }
}

__global__ void k_scan_add(void) {
    int tid = threadIdx.x;
    int base = blockIdx.x * SCAN_CHUNK + tid * 4;
    int add = g_bsum[blockIdx.x];
#pragma unroll
    for (int i = 0; i < 4; i++) {
        int idx = base + i;
        if (idx < NNODES) g_off[idx] += add;
    }
}

__global__ void k_scatter(const int* __restrict__ src, const int* __restrict__ dst) {
    int e = blockIdx.x * blockDim.x + threadIdx.x;
    if (e >= NEDGES) return;
    int s = src[e], d = dst[e];
    int pos = g_off[d] + atomicAdd(&g_cursor[d], 1);
    g_csr[pos] = make_int2(s, __float_as_int(g_dinv[s] * g_dinv[d]));
}

// ---------------- SGEMM: C[M,BN] = A[M,128] @ B[128,BN] ----------------------
// Software-pipelined: double-buffered smem, register staging, 1 sync per k-step.
template <int BN>
__global__ __launch_bounds__(256, 2) void k_sgemm(const float* __restrict__ A,
                                                  const float* __restrict__ B,
                                                  float* __restrict__ C, int M) {
    constexpr int BM = 128, BK = 8, TM = 8, TN = BN / 16;
    constexpr int NSTEP = 128 / BK;  // 16
    __shared__ float As[2][BK][BM + 4];
    __shared__ float Bs[2][BK][BN];

    int tid = threadIdx.x;
    int ty = tid / 16, tx = tid % 16;
    int blockRow = blockIdx.x * BM;

    float acc[TM][TN];
#pragma unroll
    for (int i = 0; i < TM; i++)
#pragma unroll
        for (int j = 0; j < TN; j++) acc[i][j] = 0.0f;

    int arow = tid >> 1;
    int acol = (tid & 1) * 4;
    int brow = tid / (BN / 4);
    int bcol = (tid % (BN / 4)) * 4;
    bool bload = (BN == 128) || (tid < 128);
    bool aload = (blockRow + arow < M);

    const float* aptr = &A[(size_t)(blockRow + arow) * 128 + acol];
    const float* bptr = &B[(size_t)brow * BN + bcol];

    // prologue: stage k-step 0
    {
        float4 a = make_float4(0.f, 0.f, 0.f, 0.f);
        if (aload) a = *reinterpret_cast<const float4*>(aptr);
        As[0][acol + 0][arow] = a.x;
        As[0][acol + 1][arow] = a.y;
        As[0][acol + 2][arow] = a.z;
        As[0][acol + 3][arow] = a.w;
        if (bload)
            *reinterpret_cast<float4*>(&Bs[0][brow][bcol]) =
                *reinterpret_cast<const float4*>(bptr);
    }
    __syncthreads();

    int cur = 0;
#pragma unroll 2
    for (int s = 0; s < NSTEP; s++) {
        float4 an, bn;
        bool has = (s + 1 < NSTEP);
        if (has) {
            an = make_float4(0.f, 0.f, 0.f, 0.f);
            if (aload) an = *reinterpret_cast<const float4*>(aptr + (s + 1) * BK);
            if (bload) bn = *reinterpret_cast<const float4*>(bptr + (size_t)(s + 1) * BK * BN);
        }

#pragma unroll
        for (int kk = 0; kk < BK; kk++) {
            float ar[TM], br[TN];
            const float4* ap = reinterpret_cast<const float4*>(&As[cur][kk][ty * TM]);
            float4 a0 = ap[0], a1 = ap[1];
            ar[0] = a0.x; ar[1] = a0.y; ar[2] = a0.z; ar[3] = a0.w;
            ar[4] = a1.x; ar[5] = a1.y; ar[6] = a1.z; ar[7] = a1.w;
            const float4* bp = reinterpret_cast<const float4*>(&Bs[cur][kk][tx * TN]);
#pragma unroll
            for (int j4 = 0; j4 < TN / 4; j4++) {
                float4 b4 = bp[j4];
                br[j4 * 4 + 0] = b4.x; br[j4 * 4 + 1] = b4.y;
                br[j4 * 4 + 2] = b4.z; br[j4 * 4 + 3] = b4.w;
            }
#pragma unroll
            for (int i = 0; i < TM; i++)
#pragma unroll
                for (int j = 0; j < TN; j++) acc[i][j] += ar[i] * br[j];
        }

        if (has) {
            int nxt = cur ^ 1;
            As[nxt][acol + 0][arow] = an.x;
            As[nxt][acol + 1][arow] = an.y;
            As[nxt][acol + 2][arow] = an.z;
            As[nxt][acol + 3][arow] = an.w;
            if (bload)
                *reinterpret_cast<float4*>(&Bs[nxt][brow][bcol]) = bn;
            __syncthreads();
            cur = nxt;
        }
    }

#pragma unroll
    for (int i = 0; i < TM; i++) {
        int row = blockRow + ty * TM + i;
        if (row >= M) continue;
#pragma unroll
        for (int j4 = 0; j4 < TN / 4; j4++) {
            float4 o;
            o.x = acc[i][j4 * 4 + 0]; o.y = acc[i][j4 * 4 + 1];
            o.z = acc[i][j4 * 4 + 2]; o.w = acc[i][j4 * 4 + 3];
            *reinterpret_cast<float4*>(&C[(size_t)row * BN + tx * TN + j4 * 4]) = o;
        }
    }
}

// ---------------- Aggregation: out[v] = sum_{(s,v)} w * h[s] (+self) + bias ---
// one warp per dst node; packed int2 edge records (src, weight)
template <int DIM, bool RELU>
__global__ __launch_bounds__(256) void k_agg(const float* __restrict__ h,
                                             const float* __restrict__ bias,
                                             float* __restrict__ out) {
    int warp = (blockIdx.x * blockDim.x + threadIdx.x) >> 5;
    if (warp >= NNODES) return;
    int lane = threadIdx.x & 31;

    float dv = g_dinv[warp];
    float wself = dv * dv;
    int beg = g_off[warp];
    int end = beg + (g_deg[warp] - 1);
    const int2* __restrict__ cp = g_csr;

    if (DIM == 128) {
        const float4* hp = reinterpret_cast<const float4*>(h);
        float4 sv = hp[(size_t)warp * 32 + lane];
        float ax = sv.x * wself, ay = sv.y * wself, az = sv.z * wself, aw = sv.w * wself;
        int e = beg;
        for (; e + 3 < end; e += 4) {
            int2 p0 = cp[e], p1 = cp[e + 1], p2 = cp[e + 2], p3 = cp[e + 3];
            float w0 = __int_as_float(p0.y), w1 = __int_as_float(p1.y);
            float w2 = __int_as_float(p2.y), w3 = __int_as_float(p3.y);
            float4 v0 = hp[(size_t)p0.x * 32 + lane];
            float4 v1 = hp[(size_t)p1.x * 32 + lane];
            float4 v2 = hp[(size_t)p2.x * 32 + lane];
            float4 v3 = hp[(size_t)p3.x * 32 + lane];
            ax += v0.x * w0 + v1.x * w1 + v2.x * w2 + v3.x * w3;
            ay += v0.y * w0 + v1.y * w1 + v2.y * w2 + v3.y * w3;
            az += v0.z * w0 + v1.z * w1 + v2.z * w2 + v3.z * w3;
            aw += v0.w * w0 + v1.w * w1 + v2.w * w2 + v3.w * w3;
        }
        for (; e < end; e++) {
            int2 p0 = cp[e];
            float w0 = __int_as_float(p0.y);
            float4 v0 = hp[(size_t)p0.x * 32 + lane];
            ax += v0.x * w0; ay += v0.y * w0; az += v0.z * w0; aw += v0.w * w0;
        }
        float4 b4 = reinterpret_cast<const float4*>(bias)[lane];
        ax += b4.x; ay += b4.y; az += b4.z; aw += b4.w;
        if (RELU) {
            ax = fmaxf(ax, 0.f); ay = fmaxf(ay, 0.f);
            az = fmaxf(az, 0.f); aw = fmaxf(aw, 0.f);
        }
        float4 o; o.x = ax; o.y = ay; o.z = az; o.w = aw;
        reinterpret_cast<float4*>(out)[(size_t)warp * 32 + lane] = o;
    } else {  // DIM == 64
        const float2* hp = reinterpret_cast<const float2*>(h);
        float2 sv = hp[(size_t)warp * 32 + lane];
        float ax = sv.x * wself, ay = sv.y * wself;
        int e = beg;
        for (; e + 3 < end; e += 4) {
            int2 p0 = cp[e], p1 = cp[e + 1], p2 = cp[e + 2], p3 = cp[e + 3];
            float w0 = __int_as_float(p0.y), w1 = __int_as_float(p1.y);
            float w2 = __int_as_float(p2.y), w3 = __int_as_float(p3.y);
            float2 v0 = hp[(size_t)p0.x * 32 + lane];
            float2 v1 = hp[(size_t)p1.x * 32 + lane];
            float2 v2 = hp[(size_t)p2.x * 32 + lane];
            float2 v3 = hp[(size_t)p3.x * 32 + lane];
            ax += v0.x * w0 + v1.x * w1 + v2.x * w2 + v3.x * w3;
            ay += v0.y * w0 + v1.y * w1 + v2.y * w2 + v3.y * w3;
        }
        for (; e < end; e++) {
            int2 p0 = cp[e];
            float w0 = __int_as_float(p0.y);
            float2 v0 = hp[(size_t)p0.x * 32 + lane];
            ax += v0.x * w0; ay += v0.y * w0;
        }
        float2 b2 = reinterpret_cast<const float2*>(bias)[lane];
        ax += b2.x; ay += b2.y;
        if (RELU) { ax = fmaxf(ax, 0.f); ay = fmaxf(ay, 0.f); }
        float2 o; o.x = ax; o.y = ay;
        reinterpret_cast<float2*>(out)[(size_t)warp * 32 + lane] = o;
    }
}

// ---------------- launch ------------------------------------------------------
extern "C" void kernel_launch(void* const* d_in, const int* in_sizes, int n_in,
                              void* d_out, int out_size) {
    const float* x  = (const float*)d_in[0];
    const int*   ei = (const int*)d_in[1];
    const float* W1 = (const float*)d_in[2];
    const float* b1 = (const float*)d_in[3];
    const float* W2 = (const float*)d_in[4];
    const float* b2 = (const float*)d_in[5];
    const float* W3 = (const float*)d_in[6];
    const float* b3 = (const float*)d_in[7];
    float* out = (float*)d_out;

    const int* src = ei;
    const int* dst = ei + NEDGES;

    float* bufA; cudaGetSymbolAddress((void**)&bufA, g_bufA);
    float* bufB; cudaGetSymbolAddress((void**)&bufB, g_bufB);

    const int TB = 256;
    int nodeBlocks = (NNODES + TB - 1) / TB;   // 391
    int edgeBlocks = (NEDGES + TB - 1) / TB;   // 6250
    int gemmBlocks = (NNODES + 127) / 128;     // 782
    int aggBlocks  = (NNODES + 7) / 8;         // 12500 (8 warps/block)

    // k_sgemm<128> is the 4th launch -> the ncu-profiled launch
    k_init<<<nodeBlocks, TB>>>();
    k_count<<<edgeBlocks, TB>>>(dst);
    k_scan_block<<<SCAN_BLOCKS, TB>>>();                          // also fills g_dinv
    k_sgemm<128><<<gemmBlocks, TB>>>(x, W1, bufA, NNODES);        // 4th (profiled)
    k_scan_top<<<1, 1>>>();
    k_scan_add<<<SCAN_BLOCKS, TB>>>();
    k_scatter<<<edgeBlocks, TB>>>(src, dst);

    k_agg<128, true><<<aggBlocks, TB>>>(bufA, b1, bufB);
    k_sgemm<128><<<gemmBlocks, TB>>>(bufB, W2, bufA, NNODES);
    k_agg<128, true><<<aggBlocks, TB>>>(bufA, b2, bufB);
    k_sgemm<64><<<gemmBlocks, TB>>>(bufB, W3, bufA, NNODES);
    k_agg<64, false><<<aggBlocks, TB>>>(bufA, b3, out);
}

// round 7
// speedup vs baseline: 1.5036x; 1.0233x over previous
#include <cuda_runtime.h>
#include <cuda_bf16.h>
#include <cstdint>

#define NNODES 100000
#define NEDGES 1600000
#define DIN 128
#define DH 128
#define DOUT 64

typedef unsigned long long u64;
typedef unsigned int u32;

// bf16 pitch for MMA operand rows: 136 bf16 = 272 B; 272 mod 128 = 16 ->
// fragment banks = (4g + t) mod 32: conflict-free
#define PITCHB 272

// ---------------- scratch (device globals; no allocation allowed) -------------
__device__ int   g_deg[NNODES];
__device__ float g_dinv[NNODES];
__device__ int   g_off[NNODES];
__device__ int   g_cursor[NNODES];
__device__ int2  g_csr[NEDGES];          // packed {src, bitcast(weight)}
__device__ float g_bufA[(size_t)NNODES * DIN];
__device__ float g_bufB[(size_t)NNODES * DIN];

// pre-split, pre-transposed bf16 weight images: [n][k] rows, 272B pitch
__device__ __align__(16) char g_W1hi[128 * PITCHB], g_W1lo[128 * PITCHB];
__device__ __align__(16) char g_W2hi[128 * PITCHB], g_W2lo[128 * PITCHB];
__device__ __align__(16) char g_W3hi[64 * PITCHB],  g_W3lo[64 * PITCHB];

#define SCAN_CHUNK 1024
#define SCAN_BLOCKS 98
__device__ int g_bsum[SCAN_BLOCKS];

// ---------------- helpers ------------------------------------------------------
__device__ __forceinline__ void split4(float4 v, u64& hi, u64& lo) {
    __nv_bfloat16 hx = __float2bfloat16_rn(v.x);
    __nv_bfloat16 hy = __float2bfloat16_rn(v.y);
    __nv_bfloat16 hz = __float2bfloat16_rn(v.z);
    __nv_bfloat16 hw = __float2bfloat16_rn(v.w);
    __nv_bfloat16 lx = __float2bfloat16_rn(v.x - __bfloat162float(hx));
    __nv_bfloat16 ly = __float2bfloat16_rn(v.y - __bfloat162float(hy));
    __nv_bfloat16 lz = __float2bfloat16_rn(v.z - __bfloat162float(hz));
    __nv_bfloat16 lw = __float2bfloat16_rn(v.w - __bfloat162float(hw));
    hi = (u64)__bfloat16_as_ushort(hx) | ((u64)__bfloat16_as_ushort(hy) << 16)
       | ((u64)__bfloat16_as_ushort(hz) << 32) | ((u64)__bfloat16_as_ushort(hw) << 48);
    lo = (u64)__bfloat16_as_ushort(lx) | ((u64)__bfloat16_as_ushort(ly) << 16)
       | ((u64)__bfloat16_as_ushort(lz) << 32) | ((u64)__bfloat16_as_ushort(lw) << 48);
}

#define MMA16816(c, a, b) \
    asm volatile( \
        "mma.sync.aligned.m16n8k16.row.col.f32.bf16.bf16.f32 " \
        "{%0,%1,%2,%3}, {%4,%5,%6,%7}, {%8,%9}, {%0,%1,%2,%3};" \
        : "+f"((c)[0]), "+f"((c)[1]), "+f"((c)[2]), "+f"((c)[3]) \
        : "r"((a)[0]), "r"((a)[1]), "r"((a)[2]), "r"((a)[3]), \
          "r"((b)[0]), "r"((b)[1]))

// ---------------- weight prep: [n][k] bf16 hi/lo pitched images ---------------
template <int BN>
__global__ void k_prepW(const float* __restrict__ W, char* __restrict__ hi_img,
                        char* __restrict__ lo_img) {
    int i = blockIdx.x * blockDim.x + threadIdx.x;  // (n, k4)
    if (i >= BN * 32) return;
    int n = i >> 5;
    int k4 = (i & 31) * 4;
    float4 v;
    v.x = W[(size_t)(k4 + 0) * BN + n];
    v.y = W[(size_t)(k4 + 1) * BN + n];
    v.z = W[(size_t)(k4 + 2) * BN + n];
    v.w = W[(size_t)(k4 + 3) * BN + n];
    u64 hi, lo;
    split4(v, hi, lo);
    size_t off = (size_t)n * PITCHB + (size_t)k4 * 2;
    *reinterpret_cast<u64*>(hi_img + off) = hi;
    *reinterpret_cast<u64*>(lo_img + off) = lo;
}

// ---------------- mma.sync GEMM v2: 512 thr, warp tile 32x32 -----------------
// C[M,BN] = A[M,128] @ W[128,BN], bf16x3 split (Ahi*Bhi + Ahi*Blo + Alo*Bhi).
// Full K resident in smem; one sync; 16 warps (4/SMSP) for latency hiding.
template <int BN>
__global__ __launch_bounds__(512, 1) void k_mma(const float* __restrict__ A,
                                                const char* __restrict__ BhiImg,
                                                const char* __restrict__ BloImg,
                                                float* __restrict__ C, int M) {
    extern __shared__ char smem[];
    constexpr int A_BYTES = 128 * PITCHB;     // 34816
    constexpr int B_BYTES = BN * PITCHB;
    char* sAhi = smem;
    char* sAlo = smem + A_BYTES;
    char* sBhi = smem + 2 * A_BYTES;
    char* sBlo = sBhi + B_BYTES;

    int tid = threadIdx.x;
    int blockRow = blockIdx.x * 128;

    // load + split A tile (8 float4 per thread, coalesced)
    for (int i = tid; i < 128 * 32; i += 512) {
        int row = i >> 5;
        int c4 = (i & 31) * 4;
        float4 v = make_float4(0.f, 0.f, 0.f, 0.f);
        int grow = blockRow + row;
        if (grow < M)
            v = *reinterpret_cast<const float4*>(&A[(size_t)grow * 128 + c4]);
        u64 hi, lo;
        split4(v, hi, lo);
        size_t off = (size_t)row * PITCHB + (size_t)c4 * 2;
        *reinterpret_cast<u64*>(sAhi + off) = hi;
        *reinterpret_cast<u64*>(sAlo + off) = lo;
    }
    // raw-copy pre-split weight images
    {
        const float4* sH = reinterpret_cast<const float4*>(BhiImg);
        const float4* sL = reinterpret_cast<const float4*>(BloImg);
        float4* dH = reinterpret_cast<float4*>(sBhi);
        float4* dL = reinterpret_cast<float4*>(sBlo);
        for (int i = tid; i < BN * 17; i += 512) {  // BN*272/16
            dH[i] = sH[i];
            dL[i] = sL[i];
        }
    }
    __syncthreads();

    int wid = tid >> 5, lane = tid & 31;
    int g = lane >> 2, t = lane & 3;
    constexpr int WN = BN / 4;        // 32 (BN=128) or 16 (BN=64)
    constexpr int NT = WN / 8;        // 4 or 2
    int wm = wid & 3, wn = wid >> 2;
    int rowbase = wm * 32;
    int colbase = wn * WN;

    float c[2][NT][4];
#pragma unroll
    for (int mt = 0; mt < 2; mt++)
#pragma unroll
        for (int nt = 0; nt < NT; nt++)
#pragma unroll
            for (int j = 0; j < 4; j++) c[mt][nt][j] = 0.f;

#pragma unroll
    for (int term = 0; term < 3; term++) {
        const char* Ab = (term == 2) ? sAlo : sAhi;
        const char* Bb = (term == 1) ? sBlo : sBhi;
#pragma unroll
        for (int k0 = 0; k0 < 128; k0 += 16) {
            u32 a[2][4];
#pragma unroll
            for (int mt = 0; mt < 2; mt++) {
                const char* base = Ab + (size_t)(rowbase + mt * 16 + g) * PITCHB + k0 * 2;
                a[mt][0] = *reinterpret_cast<const u32*>(base + t * 4);
                a[mt][1] = *reinterpret_cast<const u32*>(base + 8 * PITCHB + t * 4);
                a[mt][2] = *reinterpret_cast<const u32*>(base + t * 4 + 16);
                a[mt][3] = *reinterpret_cast<const u32*>(base + 8 * PITCHB + t * 4 + 16);
            }
            u32 b[NT][2];
#pragma unroll
            for (int nt = 0; nt < NT; nt++) {
                const char* bb = Bb + (size_t)(colbase + nt * 8 + g) * PITCHB + k0 * 2;
                b[nt][0] = *reinterpret_cast<const u32*>(bb + t * 4);
                b[nt][1] = *reinterpret_cast<const u32*>(bb + t * 4 + 16);
            }
#pragma unroll
            for (int mt = 0; mt < 2; mt++)
#pragma unroll
                for (int nt = 0; nt < NT; nt++) MMA16816(c[mt][nt], a[mt], b[nt]);
        }
    }

    // epilogue: fragment-owner float2 stores
#pragma unroll
    for (int mt = 0; mt < 2; mt++) {
        int row = blockRow + rowbase + mt * 16 + g;
#pragma unroll
        for (int nt = 0; nt < NT; nt++) {
            int col = colbase + nt * 8 + 2 * t;
            if (row < M) {
                float2 o; o.x = c[mt][nt][0]; o.y = c[mt][nt][1];
                *reinterpret_cast<float2*>(&C[(size_t)row * BN + col]) = o;
            }
            if (row + 8 < M) {
                float2 o; o.x = c[mt][nt][2]; o.y = c[mt][nt][3];
                *reinterpret_cast<float2*>(&C[(size_t)(row + 8) * BN + col]) = o;
            }
        }
    }
}

// ---------------- CSR build ---------------------------------------------------
__global__ void k_init(void) {
    int v = blockIdx.x * blockDim.x + threadIdx.x;
    if (v < NNODES) { g_deg[v] = 1; g_cursor[v] = 0; }
}
__global__ void k_count(const int* __restrict__ dst) {
    int e = blockIdx.x * blockDim.x + threadIdx.x;
    if (e < NEDGES) atomicAdd(&g_deg[dst[e]], 1);
}
__global__ void k_scan_block(void) {
    __shared__ int wsum[8];
    int tid = threadIdx.x;
    int base = blockIdx.x * SCAN_CHUNK + tid * 4;
    int v[4];
#pragma unroll
    for (int i = 0; i < 4; i++) {
        int idx = base + i;
        v[i] = (idx < NNODES) ? (g_deg[idx] - 1) : 0;
        if (idx < NNODES) g_dinv[idx] = rsqrtf((float)(v[i] + 1));
    }
    int e0 = 0, e1 = v[0], e2 = v[0] + v[1], e3 = v[0] + v[1] + v[2];
    int tot = e3 + v[3];
    int lane = tid & 31, wid = tid >> 5;
    int x = tot;
#pragma unroll
    for (int off = 1; off < 32; off <<= 1) {
        int y = __shfl_up_sync(0xFFFFFFFFu, x, off);
        if (lane >= off) x += y;
    }
    if (lane == 31) wsum[wid] = x;
    __syncthreads();
    if (wid == 0) {
        int tt = (lane < 8) ? wsum[lane] : 0;
        int xx = tt;
#pragma unroll
        for (int off = 1; off < 8; off <<= 1) {
            int y = __shfl_up_sync(0xFFFFFFFFu, xx, off);
            if (lane >= off) xx += y;
        }
        if (lane < 8) wsum[lane] = xx - tt;
    }
    __syncthreads();
    int texc = wsum[wid] + (x - tot);
    if (base + 0 < NNODES) g_off[base + 0] = texc + e0;
    if (base + 1 < NNODES) g_off[base + 1] = texc + e1;
    if (base + 2 < NNODES) g_off[base + 2] = texc + e2;
    if (base + 3 < NNODES) g_off[base + 3] = texc + e3;
    if (tid == blockDim.x - 1) g_bsum[blockIdx.x] = texc + tot;
}
__global__ void k_scan_top(void) {
    int acc = 0;
    for (int b = 0; b < SCAN_BLOCKS; b++) {
        int t = g_bsum[b];
        g_bsum[b] = acc;
        acc += t;
    }
}
__global__ void k_scan_add(void) {
    int tid = threadIdx.x;
    int base = blockIdx.x * SCAN_CHUNK + tid * 4;
    int add = g_bsum[blockIdx.x];
#pragma unroll
    for (int i = 0; i < 4; i++) {
        int idx = base + i;
        if (idx < NNODES) g_off[idx] += add;
    }
}
__global__ void k_scatter(const int* __restrict__ src, const int* __restrict__ dst) {
    int e = blockIdx.x * blockDim.x + threadIdx.x;
    if (e >= NEDGES) return;
    int s = src[e], d = dst[e];
    int pos = g_off[d] + atomicAdd(&g_cursor[d], 1);
    g_csr[pos] = make_int2(s, __float_as_int(g_dinv[s] * g_dinv[d]));
}

// ---------------- Aggregation -------------------------------------------------
template <int DIM, bool RELU>
__global__ __launch_bounds__(256) void k_agg(const float* __restrict__ h,
                                             const float* __restrict__ bias,
                                             float* __restrict__ out) {
    int warp = (blockIdx.x * blockDim.x + threadIdx.x) >> 5;
    if (warp >= NNODES) return;
    int lane = threadIdx.x & 31;

    float dv = g_dinv[warp];
    float wself = dv * dv;
    int beg = g_off[warp];
    int end = beg + (g_deg[warp] - 1);
    const int2* __restrict__ cp = g_csr;

    if (DIM == 128) {
        const float4* hp = reinterpret_cast<const float4*>(h);
        float4 sv = hp[(size_t)warp * 32 + lane];
        float ax = sv.x * wself, ay = sv.y * wself, az = sv.z * wself, aw = sv.w * wself;
        int e = beg;
        for (; e + 3 < end; e += 4) {
            int2 p0 = cp[e], p1 = cp[e + 1], p2 = cp[e + 2], p3 = cp[e + 3];
            float w0 = __int_as_float(p0.y), w1 = __int_as_float(p1.y);
            float w2 = __int_as_float(p2.y), w3 = __int_as_float(p3.y);
            float4 v0 = hp[(size_t)p0.x * 32 + lane];
            float4 v1 = hp[(size_t)p1.x * 32 + lane];
            float4 v2 = hp[(size_t)p2.x * 32 + lane];
            float4 v3 = hp[(size_t)p3.x * 32 + lane];
            ax += v0.x * w0 + v1.x * w1 + v2.x * w2 + v3.x * w3;
            ay += v0.y * w0 + v1.y * w1 + v2.y * w2 + v3.y * w3;
            az += v0.z * w0 + v1.z * w1 + v2.z * w2 + v3.z * w3;
            aw += v0.w * w0 + v1.w * w1 + v2.w * w2 + v3.w * w3;
        }
        for (; e < end; e++) {
            int2 p0 = cp[e];
            float w0 = __int_as_float(p0.y);
            float4 v0 = hp[(size_t)p0.x * 32 + lane];
            ax += v0.x * w0; ay += v0.y * w0; az += v0.z * w0; aw += v0.w * w0;
        }
        float4 b4 = reinterpret_cast<const float4*>(bias)[lane];
        ax += b4.x; ay += b4.y; az += b4.z; aw += b4.w;
        if (RELU) {
            ax = fmaxf(ax, 0.f); ay = fmaxf(ay, 0.f);
            az = fmaxf(az, 0.f); aw = fmaxf(aw, 0.f);
        }
        float4 o; o.x = ax; o.y = ay; o.z = az; o.w = aw;
        reinterpret_cast<float4*>(out)[(size_t)warp * 32 + lane] = o;
    } else {  // DIM == 64
        const float2* hp = reinterpret_cast<const float2*>(h);
        float2 sv = hp[(size_t)warp * 32 + lane];
        float ax = sv.x * wself, ay = sv.y * wself;
        int e = beg;
        for (; e + 3 < end; e += 4) {
            int2 p0 = cp[e], p1 = cp[e + 1], p2 = cp[e + 2], p3 = cp[e + 3];
            float w0 = __int_as_float(p0.y), w1 = __int_as_float(p1.y);
            float w2 = __int_as_float(p2.y), w3 = __int_as_float(p3.y);
            float2 v0 = hp[(size_t)p0.x * 32 + lane];
            float2 v1 = hp[(size_t)p1.x * 32 + lane];
            float2 v2 = hp[(size_t)p2.x * 32 + lane];
            float2 v3 = hp[(size_t)p3.x * 32 + lane];
            ax += v0.x * w0 + v1.x * w1 + v2.x * w2 + v3.x * w3;
            ay += v0.y * w0 + v1.y * w1 + v2.y * w2 + v3.y * w3;
        }
        for (; e < end; e++) {
            int2 p0 = cp[e];
            float w0 = __int_as_float(p0.y);
            float2 v0 = hp[(size_t)p0.x * 32 + lane];
            ax += v0.x * w0; ay += v0.y * w0;
        }
        float2 b2 = reinterpret_cast<const float2*>(bias)[lane];
        ax += b2.x; ay += b2.y;
        if (RELU) { ax = fmaxf(ax, 0.f); ay = fmaxf(ay, 0.f); }
        float2 o; o.x = ax; o.y = ay;
        reinterpret_cast<float2*>(out)[(size_t)warp * 32 + lane] = o;
    }
}

// ---------------- launch ------------------------------------------------------
extern "C" void kernel_launch(void* const* d_in, const int* in_sizes, int n_in,
                              void* d_out, int out_size) {
    const float* x  = (const float*)d_in[0];
    const int*   ei = (const int*)d_in[1];
    const float* W1 = (const float*)d_in[2];
    const float* b1 = (const float*)d_in[3];
    const float* W2 = (const float*)d_in[4];
    const float* b2 = (const float*)d_in[5];
    const float* W3 = (const float*)d_in[6];
    const float* b3 = (const float*)d_in[7];
    float* out = (float*)d_out;

    const int* src = ei;
    const int* dst = ei + NEDGES;

    float* bufA; cudaGetSymbolAddress((void**)&bufA, g_bufA);
    float* bufB; cudaGetSymbolAddress((void**)&bufB, g_bufB);
    char *w1h, *w1l, *w2h, *w2l, *w3h, *w3l;
    cudaGetSymbolAddress((void**)&w1h, g_W1hi); cudaGetSymbolAddress((void**)&w1l, g_W1lo);
    cudaGetSymbolAddress((void**)&w2h, g_W2hi); cudaGetSymbolAddress((void**)&w2l, g_W2lo);
    cudaGetSymbolAddress((void**)&w3h, g_W3hi); cudaGetSymbolAddress((void**)&w3l, g_W3lo);

    const int SMEM128 = 2 * 128 * PITCHB + 2 * 128 * PITCHB;  // 139264
    const int SMEM64  = 2 * 128 * PITCHB + 2 * 64 * PITCHB;   // 104448
    cudaFuncSetAttribute(k_mma<128>, cudaFuncAttributeMaxDynamicSharedMemorySize, SMEM128);
    cudaFuncSetAttribute(k_mma<64>,  cudaFuncAttributeMaxDynamicSharedMemorySize, SMEM64);

    const int TB = 256;
    int nodeBlocks = (NNODES + TB - 1) / TB;
    int edgeBlocks = (NEDGES + TB - 1) / TB;
    int gemmBlocks = (NNODES + 127) / 128;   // 782
    int aggBlocks  = (NNODES + 7) / 8;

    // k_mma<128> is the 4th launch -> the ncu-profiled launch
    k_prepW<128><<<16, TB>>>(W1, w1h, w1l);
    k_init<<<nodeBlocks, TB>>>();
    k_count<<<edgeBlocks, TB>>>(dst);
    k_mma<128><<<gemmBlocks, 512, SMEM128>>>(x, w1h, w1l, bufA, NNODES);  // 4th (profiled)
    k_scan_block<<<SCAN_BLOCKS, TB>>>();
    k_scan_top<<<1, 1>>>();
    k_scan_add<<<SCAN_BLOCKS, TB>>>();
    k_scatter<<<edgeBlocks, TB>>>(src, dst);
    k_prepW<128><<<16, TB>>>(W2, w2h, w2l);
    k_prepW<64><<<8, TB>>>(W3, w3h, w3l);

    k_agg<128, true><<<aggBlocks, TB>>>(bufA, b1, bufB);
    k_mma<128><<<gemmBlocks, 512, SMEM128>>>(bufB, w2h, w2l, bufA, NNODES);
    k_agg<128, true><<<aggBlocks, TB>>>(bufA, b2, bufB);
    k_mma<64><<<gemmBlocks, 512, SMEM64>>>(bufB, w3h, w3l, bufA, NNODES);
    k_agg<64, false><<<aggBlocks, TB>>>(bufA, b3, out);
}

// round 8
// speedup vs baseline: 1.6747x; 1.1138x over previous
#include <cuda_runtime.h>
#include <cuda_bf16.h>
#include <cstdint>

#define NNODES 100000
#define NEDGES 1600000
#define DIN 128
#define DH 128
#define DOUT 64

typedef unsigned long long u64;
typedef unsigned int u32;

// bf16 pitch for MMA operand rows: 136 bf16 = 272 B; 272 mod 128 = 16 ->
// fragment banks = (4g + t) mod 32: conflict-free
#define PITCHB 272

// ---------------- scratch (device globals; no allocation allowed) -------------
__device__ int   g_deg[NNODES];
__device__ float g_dinv[NNODES];
__device__ int   g_off[NNODES];
__device__ int   g_cursor[NNODES];
__device__ int2  g_csr[NEDGES];          // packed {src, bitcast(weight)}
__device__ float g_bufA[(size_t)NNODES * DIN];
__device__ float g_bufB[(size_t)NNODES * DIN];

// pre-split, pre-transposed bf16 weight images: [n][k] rows, 272B pitch
__device__ __align__(16) char g_W1hi[128 * PITCHB], g_W1lo[128 * PITCHB];
__device__ __align__(16) char g_W2hi[128 * PITCHB], g_W2lo[128 * PITCHB];
__device__ __align__(16) char g_W3hi[64 * PITCHB],  g_W3lo[64 * PITCHB];

#define SCAN_CHUNK 1024
#define SCAN_BLOCKS 98
__device__ int g_bsum[SCAN_BLOCKS];

// ---------------- helpers ------------------------------------------------------
__device__ __forceinline__ void split4(float4 v, u64& hi, u64& lo) {
    __nv_bfloat16 hx = __float2bfloat16_rn(v.x);
    __nv_bfloat16 hy = __float2bfloat16_rn(v.y);
    __nv_bfloat16 hz = __float2bfloat16_rn(v.z);
    __nv_bfloat16 hw = __float2bfloat16_rn(v.w);
    __nv_bfloat16 lx = __float2bfloat16_rn(v.x - __bfloat162float(hx));
    __nv_bfloat16 ly = __float2bfloat16_rn(v.y - __bfloat162float(hy));
    __nv_bfloat16 lz = __float2bfloat16_rn(v.z - __bfloat162float(hz));
    __nv_bfloat16 lw = __float2bfloat16_rn(v.w - __bfloat162float(hw));
    hi = (u64)__bfloat16_as_ushort(hx) | ((u64)__bfloat16_as_ushort(hy) << 16)
       | ((u64)__bfloat16_as_ushort(hz) << 32) | ((u64)__bfloat16_as_ushort(hw) << 48);
    lo = (u64)__bfloat16_as_ushort(lx) | ((u64)__bfloat16_as_ushort(ly) << 16)
       | ((u64)__bfloat16_as_ushort(lz) << 32) | ((u64)__bfloat16_as_ushort(lw) << 48);
}

#define MMA16816(c, a, b) \
    asm volatile( \
        "mma.sync.aligned.m16n8k16.row.col.f32.bf16.bf16.f32 " \
        "{%0,%1,%2,%3}, {%4,%5,%6,%7}, {%8,%9}, {%0,%1,%2,%3};" \
        : "+f"((c)[0]), "+f"((c)[1]), "+f"((c)[2]), "+f"((c)[3]) \
        : "r"((a)[0]), "r"((a)[1]), "r"((a)[2]), "r"((a)[3]), \
          "r"((b)[0]), "r"((b)[1]))

// ---------------- weight prep: [n][k] bf16 hi/lo pitched images ---------------
template <int BN>
__global__ void k_prepW(const float* __restrict__ W, char* __restrict__ hi_img,
                        char* __restrict__ lo_img) {
    int i = blockIdx.x * blockDim.x + threadIdx.x;  // (n, k4)
    if (i >= BN * 32) return;
    int n = i >> 5;
    int k4 = (i & 31) * 4;
    float4 v;
    v.x = W[(size_t)(k4 + 0) * BN + n];
    v.y = W[(size_t)(k4 + 1) * BN + n];
    v.z = W[(size_t)(k4 + 2) * BN + n];
    v.w = W[(size_t)(k4 + 3) * BN + n];
    u64 hi, lo;
    split4(v, hi, lo);
    size_t off = (size_t)n * PITCHB + (size_t)k4 * 2;
    *reinterpret_cast<u64*>(hi_img + off) = hi;
    *reinterpret_cast<u64*>(lo_img + off) = lo;
}

// ---------------- mma.sync GEMM v3: fused single-K-pass 3-term ---------------
// C[M,BN] = A[M,128] @ W[128,BN]; per k-step load ahi/alo/bhi/blo once,
// issue 24 MMAs (Ahi*Bhi + Ahi*Blo + Alo*Bhi). 512 thr, warp tile 32 x WN.
template <int BN>
__global__ __launch_bounds__(512, 1) void k_mma(const float* __restrict__ A,
                                                const char* __restrict__ BhiImg,
                                                const char* __restrict__ BloImg,
                                                float* __restrict__ C, int M) {
    extern __shared__ char smem[];
    constexpr int A_BYTES = 128 * PITCHB;     // 34816
    constexpr int B_BYTES = BN * PITCHB;
    char* sAhi = smem;
    char* sAlo = smem + A_BYTES;
    char* sBhi = smem + 2 * A_BYTES;
    char* sBlo = sBhi + B_BYTES;

    int tid = threadIdx.x;
    int blockRow = blockIdx.x * 128;

    // load + split A tile (8 float4 per thread, coalesced)
    for (int i = tid; i < 128 * 32; i += 512) {
        int row = i >> 5;
        int c4 = (i & 31) * 4;
        float4 v = make_float4(0.f, 0.f, 0.f, 0.f);
        int grow = blockRow + row;
        if (grow < M)
            v = *reinterpret_cast<const float4*>(&A[(size_t)grow * 128 + c4]);
        u64 hi, lo;
        split4(v, hi, lo);
        size_t off = (size_t)row * PITCHB + (size_t)c4 * 2;
        *reinterpret_cast<u64*>(sAhi + off) = hi;
        *reinterpret_cast<u64*>(sAlo + off) = lo;
    }
    // raw-copy pre-split weight images (L2-resident, shared by all CTAs)
    {
        const float4* sH = reinterpret_cast<const float4*>(BhiImg);
        const float4* sL = reinterpret_cast<const float4*>(BloImg);
        float4* dH = reinterpret_cast<float4*>(sBhi);
        float4* dL = reinterpret_cast<float4*>(sBlo);
        for (int i = tid; i < BN * 17; i += 512) {  // BN*272/16
            dH[i] = sH[i];
            dL[i] = sL[i];
        }
    }
    __syncthreads();

    int wid = tid >> 5, lane = tid & 31;
    int g = lane >> 2, t = lane & 3;
    constexpr int WN = BN / 4;        // 32 (BN=128) or 16 (BN=64)
    constexpr int NT = WN / 8;        // 4 or 2
    int wm = wid & 3, wn = wid >> 2;
    int rowbase = wm * 32;
    int colbase = wn * WN;

    float c[2][NT][4];
#pragma unroll
    for (int mt = 0; mt < 2; mt++)
#pragma unroll
        for (int nt = 0; nt < NT; nt++)
#pragma unroll
            for (int j = 0; j < 4; j++) c[mt][nt][j] = 0.f;

#pragma unroll
    for (int k0 = 0; k0 < 128; k0 += 16) {
        u32 ah[2][4], al[2][4];
#pragma unroll
        for (int mt = 0; mt < 2; mt++) {
            size_t roff = (size_t)(rowbase + mt * 16 + g) * PITCHB + k0 * 2;
            const char* bh_ = sAhi + roff;
            const char* bl_ = sAlo + roff;
            ah[mt][0] = *reinterpret_cast<const u32*>(bh_ + t * 4);
            ah[mt][1] = *reinterpret_cast<const u32*>(bh_ + 8 * PITCHB + t * 4);
            ah[mt][2] = *reinterpret_cast<const u32*>(bh_ + t * 4 + 16);
            ah[mt][3] = *reinterpret_cast<const u32*>(bh_ + 8 * PITCHB + t * 4 + 16);
            al[mt][0] = *reinterpret_cast<const u32*>(bl_ + t * 4);
            al[mt][1] = *reinterpret_cast<const u32*>(bl_ + 8 * PITCHB + t * 4);
            al[mt][2] = *reinterpret_cast<const u32*>(bl_ + t * 4 + 16);
            al[mt][3] = *reinterpret_cast<const u32*>(bl_ + 8 * PITCHB + t * 4 + 16);
        }
        u32 bh[NT][2], bl[NT][2];
#pragma unroll
        for (int nt = 0; nt < NT; nt++) {
            size_t coff = (size_t)(colbase + nt * 8 + g) * PITCHB + k0 * 2;
            const char* hh = sBhi + coff;
            const char* ll = sBlo + coff;
            bh[nt][0] = *reinterpret_cast<const u32*>(hh + t * 4);
            bh[nt][1] = *reinterpret_cast<const u32*>(hh + t * 4 + 16);
            bl[nt][0] = *reinterpret_cast<const u32*>(ll + t * 4);
            bl[nt][1] = *reinterpret_cast<const u32*>(ll + t * 4 + 16);
        }
        // 24 MMAs per k-step: hi*hi, hi*lo, lo*hi
#pragma unroll
        for (int mt = 0; mt < 2; mt++)
#pragma unroll
            for (int nt = 0; nt < NT; nt++) MMA16816(c[mt][nt], ah[mt], bh[nt]);
#pragma unroll
        for (int mt = 0; mt < 2; mt++)
#pragma unroll
            for (int nt = 0; nt < NT; nt++) MMA16816(c[mt][nt], ah[mt], bl[nt]);
#pragma unroll
        for (int mt = 0; mt < 2; mt++)
#pragma unroll
            for (int nt = 0; nt < NT; nt++) MMA16816(c[mt][nt], al[mt], bh[nt]);
    }

    // epilogue: fragment-owner float2 stores
#pragma unroll
    for (int mt = 0; mt < 2; mt++) {
        int row = blockRow + rowbase + mt * 16 + g;
#pragma unroll
        for (int nt = 0; nt < NT; nt++) {
            int col = colbase + nt * 8 + 2 * t;
            if (row < M) {
                float2 o; o.x = c[mt][nt][0]; o.y = c[mt][nt][1];
                *reinterpret_cast<float2*>(&C[(size_t)row * BN + col]) = o;
            }
            if (row + 8 < M) {
                float2 o; o.x = c[mt][nt][2]; o.y = c[mt][nt][3];
                *reinterpret_cast<float2*>(&C[(size_t)(row + 8) * BN + col]) = o;
            }
        }
    }
}

// ---------------- CSR build ---------------------------------------------------
__global__ void k_init(void) {
    int v = blockIdx.x * blockDim.x + threadIdx.x;
    if (v < NNODES) { g_deg[v] = 1; g_cursor[v] = 0; }
}
__global__ void k_count(const int* __restrict__ dst) {
    int e = blockIdx.x * blockDim.x + threadIdx.x;
    if (e < NEDGES) atomicAdd(&g_deg[dst[e]], 1);
}
__global__ void k_scan_block(void) {
    __shared__ int wsum[8];
    int tid = threadIdx.x;
    int base = blockIdx.x * SCAN_CHUNK + tid * 4;
    int v[4];
#pragma unroll
    for (int i = 0; i < 4; i++) {
        int idx = base + i;
        v[i] = (idx < NNODES) ? (g_deg[idx] - 1) : 0;
        if (idx < NNODES) g_dinv[idx] = rsqrtf((float)(v[i] + 1));
    }
    int e0 = 0, e1 = v[0], e2 = v[0] + v[1], e3 = v[0] + v[1] + v[2];
    int tot = e3 + v[3];
    int lane = tid & 31, wid = tid >> 5;
    int x = tot;
#pragma unroll
    for (int off = 1; off < 32; off <<= 1) {
        int y = __shfl_up_sync(0xFFFFFFFFu, x, off);
        if (lane >= off) x += y;
    }
    if (lane == 31) wsum[wid] = x;
    __syncthreads();
    if (wid == 0) {
        int tt = (lane < 8) ? wsum[lane] : 0;
        int xx = tt;
#pragma unroll
        for (int off = 1; off < 8; off <<= 1) {
            int y = __shfl_up_sync(0xFFFFFFFFu, xx, off);
            if (lane >= off) xx += y;
        }
        if (lane < 8) wsum[lane] = xx - tt;
    }
    __syncthreads();
    int texc = wsum[wid] + (x - tot);
    if (base + 0 < NNODES) g_off[base + 0] = texc + e0;
    if (base + 1 < NNODES) g_off[base + 1] = texc + e1;
    if (base + 2 < NNODES) g_off[base + 2] = texc + e2;
    if (base + 3 < NNODES) g_off[base + 3] = texc + e3;
    if (tid == blockDim.x - 1) g_bsum[blockIdx.x] = texc + tot;
}
__global__ void k_scan_top(void) {
    int acc = 0;
    for (int b = 0; b < SCAN_BLOCKS; b++) {
        int t = g_bsum[b];
        g_bsum[b] = acc;
        acc += t;
    }
}
__global__ void k_scan_add(void) {
    int tid = threadIdx.x;
    int base = blockIdx.x * SCAN_CHUNK + tid * 4;
    int add = g_bsum[blockIdx.x];
#pragma unroll
    for (int i = 0; i < 4; i++) {
        int idx = base + i;
        if (idx < NNODES) g_off[idx] += add;
    }
}
__global__ void k_scatter(const int* __restrict__ src, const int* __restrict__ dst) {
    int e = blockIdx.x * blockDim.x + threadIdx.x;
    if (e >= NEDGES) return;
    int s = src[e], d = dst[e];
    int pos = g_off[d] + atomicAdd(&g_cursor[d], 1);
    g_csr[pos] = make_int2(s, __float_as_int(g_dinv[s] * g_dinv[d]));
}

// ---------------- Aggregation -------------------------------------------------
template <int DIM, bool RELU>
__global__ __launch_bounds__(256) void k_agg(const float* __restrict__ h,
                                             const float* __restrict__ bias,
                                             float* __restrict__ out) {
    int warp = (blockIdx.x * blockDim.x + threadIdx.x) >> 5;
    if (warp >= NNODES) return;
    int lane = threadIdx.x & 31;

    float dv = g_dinv[warp];
    float wself = dv * dv;
    int beg = g_off[warp];
    int end = beg + (g_deg[warp] - 1);
    const int2* __restrict__ cp = g_csr;

    if (DIM == 128) {
        const float4* hp = reinterpret_cast<const float4*>(h);
        float4 sv = hp[(size_t)warp * 32 + lane];
        float ax = sv.x * wself, ay = sv.y * wself, az = sv.z * wself, aw = sv.w * wself;
        int e = beg;
        for (; e + 3 < end; e += 4) {
            int2 p0 = cp[e], p1 = cp[e + 1], p2 = cp[e + 2], p3 = cp[e + 3];
            float w0 = __int_as_float(p0.y), w1 = __int_as_float(p1.y);
            float w2 = __int_as_float(p2.y), w3 = __int_as_float(p3.y);
            float4 v0 = hp[(size_t)p0.x * 32 + lane];
            float4 v1 = hp[(size_t)p1.x * 32 + lane];
            float4 v2 = hp[(size_t)p2.x * 32 + lane];
            float4 v3 = hp[(size_t)p3.x * 32 + lane];
            ax += v0.x * w0 + v1.x * w1 + v2.x * w2 + v3.x * w3;
            ay += v0.y * w0 + v1.y * w1 + v2.y * w2 + v3.y * w3;
            az += v0.z * w0 + v1.z * w1 + v2.z * w2 + v3.z * w3;
            aw += v0.w * w0 + v1.w * w1 + v2.w * w2 + v3.w * w3;
        }
        for (; e < end; e++) {
            int2 p0 = cp[e];
            float w0 = __int_as_float(p0.y);
            float4 v0 = hp[(size_t)p0.x * 32 + lane];
            ax += v0.x * w0; ay += v0.y * w0; az += v0.z * w0; aw += v0.w * w0;
        }
        float4 b4 = reinterpret_cast<const float4*>(bias)[lane];
        ax += b4.x; ay += b4.y; az += b4.z; aw += b4.w;
        if (RELU) {
            ax = fmaxf(ax, 0.f); ay = fmaxf(ay, 0.f);
            az = fmaxf(az, 0.f); aw = fmaxf(aw, 0.f);
        }
        float4 o; o.x = ax; o.y = ay; o.z = az; o.w = aw;
        reinterpret_cast<float4*>(out)[(size_t)warp * 32 + lane] = o;
    } else {  // DIM == 64
        const float2* hp = reinterpret_cast<const float2*>(h);
        float2 sv = hp[(size_t)warp * 32 + lane];
        float ax = sv.x * wself, ay = sv.y * wself;
        int e = beg;
        for (; e + 3 < end; e += 4) {
            int2 p0 = cp[e], p1 = cp[e + 1], p2 = cp[e + 2], p3 = cp[e + 3];
            float w0 = __int_as_float(p0.y), w1 = __int_as_float(p1.y);
            float w2 = __int_as_float(p2.y), w3 = __int_as_float(p3.y);
            float2 v0 = hp[(size_t)p0.x * 32 + lane];
            float2 v1 = hp[(size_t)p1.x * 32 + lane];
            float2 v2 = hp[(size_t)p2.x * 32 + lane];
            float2 v3 = hp[(size_t)p3.x * 32 + lane];
            ax += v0.x * w0 + v1.x * w1 + v2.x * w2 + v3.x * w3;
            ay += v0.y * w0 + v1.y * w1 + v2.y * w2 + v3.y * w3;
        }
        for (; e < end; e++) {
            int2 p0 = cp[e];
            float w0 = __int_as_float(p0.y);
            float2 v0 = hp[(size_t)p0.x * 32 + lane];
            ax += v0.x * w0; ay += v0.y * w0;
        }
        float2 b2 = reinterpret_cast<const float2*>(bias)[lane];
        ax += b2.x; ay += b2.y;
        if (RELU) { ax = fmaxf(ax, 0.f); ay = fmaxf(ay, 0.f); }
        float2 o; o.x = ax; o.y = ay;
        reinterpret_cast<float2*>(out)[(size_t)warp * 32 + lane] = o;
    }
}

// ---------------- launch ------------------------------------------------------
extern "C" void kernel_launch(void* const* d_in, const int* in_sizes, int n_in,
                              void* d_out, int out_size) {
    const float* x  = (const float*)d_in[0];
    const int*   ei = (const int*)d_in[1];
    const float* W1 = (const float*)d_in[2];
    const float* b1 = (const float*)d_in[3];
    const float* W2 = (const float*)d_in[4];
    const float* b2 = (const float*)d_in[5];
    const float* W3 = (const float*)d_in[6];
    const float* b3 = (const float*)d_in[7];
    float* out = (float*)d_out;

    const int* src = ei;
    const int* dst = ei + NEDGES;

    float* bufA; cudaGetSymbolAddress((void**)&bufA, g_bufA);
    float* bufB; cudaGetSymbolAddress((void**)&bufB, g_bufB);
    char *w1h, *w1l, *w2h, *w2l, *w3h, *w3l;
    cudaGetSymbolAddress((void**)&w1h, g_W1hi); cudaGetSymbolAddress((void**)&w1l, g_W1lo);
    cudaGetSymbolAddress((void**)&w2h, g_W2hi); cudaGetSymbolAddress((void**)&w2l, g_W2lo);
    cudaGetSymbolAddress((void**)&w3h, g_W3hi); cudaGetSymbolAddress((void**)&w3l, g_W3lo);

    const int SMEM128 = 2 * 128 * PITCHB + 2 * 128 * PITCHB;  // 139264
    const int SMEM64  = 2 * 128 * PITCHB + 2 * 64 * PITCHB;   // 104448
    cudaFuncSetAttribute(k_mma<128>, cudaFuncAttributeMaxDynamicSharedMemorySize, SMEM128);
    cudaFuncSetAttribute(k_mma<64>,  cudaFuncAttributeMaxDynamicSharedMemorySize, SMEM64);

    const int TB = 256;
    int nodeBlocks = (NNODES + TB - 1) / TB;
    int edgeBlocks = (NEDGES + TB - 1) / TB;
    int gemmBlocks = (NNODES + 127) / 128;   // 782
    int aggBlocks  = (NNODES + 7) / 8;

    // k_mma<128> is the 4th launch -> the ncu-profiled launch
    k_prepW<128><<<16, TB>>>(W1, w1h, w1l);
    k_init<<<nodeBlocks, TB>>>();
    k_count<<<edgeBlocks, TB>>>(dst);
    k_mma<128><<<gemmBlocks, 512, SMEM128>>>(x, w1h, w1l, bufA, NNODES);  // 4th (profiled)
    k_scan_block<<<SCAN_BLOCKS, TB>>>();
    k_scan_top<<<1, 1>>>();
    k_scan_add<<<SCAN_BLOCKS, TB>>>();
    k_scatter<<<edgeBlocks, TB>>>(src, dst);
    k_prepW<128><<<16, TB>>>(W2, w2h, w2l);
    k_prepW<64><<<8, TB>>>(W3, w3h, w3l);

    k_agg<128, true><<<aggBlocks, TB>>>(bufA, b1, bufB);
    k_mma<128><<<gemmBlocks, 512, SMEM128>>>(bufB, w2h, w2l, bufA, NNODES);
    k_agg<128, true><<<aggBlocks, TB>>>(bufA, b2, bufB);
    k_mma<64><<<gemmBlocks, 512, SMEM64>>>(bufB, w3h, w3l, bufA, NNODES);
    k_agg<64, false><<<aggBlocks, TB>>>(bufA, b3, out);
}

// round 9
// speedup vs baseline: 1.8625x; 1.1122x over previous
#include <cuda_runtime.h>
#include <cuda_bf16.h>
#include <cstdint>

#define NNODES 100000
#define NEDGES 1600000
#define DIN 128
#define DH 128
#define DOUT 64

typedef unsigned long long u64;
typedef unsigned int u32;

// bf16 pitch for MMA operand rows: 136 bf16 = 272 B; banks (4r + c/4) mod 32
// -> conflict-free fragment/ldmatrix phases
#define PITCHB 272

// ---------------- scratch (device globals; no allocation allowed) -------------
__device__ int   g_deg[NNODES];
__device__ float g_dinv[NNODES];
__device__ int   g_off[NNODES];
__device__ int   g_cursor[NNODES];
__device__ int2  g_csr[NEDGES];          // packed {src, bitcast(weight)}
__device__ float g_bufA[(size_t)NNODES * DIN];
__device__ float g_bufB[(size_t)NNODES * DIN];

// pre-split, pre-transposed bf16 weight images: [n][k] rows, 272B pitch
__device__ __align__(16) char g_W1hi[128 * PITCHB], g_W1lo[128 * PITCHB];
__device__ __align__(16) char g_W2hi[128 * PITCHB], g_W2lo[128 * PITCHB];
__device__ __align__(16) char g_W3hi[64 * PITCHB],  g_W3lo[64 * PITCHB];

#define SCAN_CHUNK 1024
#define SCAN_BLOCKS 98
__device__ int g_bsum[SCAN_BLOCKS];

// ---------------- helpers ------------------------------------------------------
__device__ __forceinline__ u32 smem_u32(const void* p) {
    u32 a;
    asm("{ .reg .u64 t; cvta.to.shared.u64 t, %1; cvt.u32.u64 %0, t; }" : "=r"(a) : "l"(p));
    return a;
}

__device__ __forceinline__ void split4(float4 v, u64& hi, u64& lo) {
    __nv_bfloat16 hx = __float2bfloat16_rn(v.x);
    __nv_bfloat16 hy = __float2bfloat16_rn(v.y);
    __nv_bfloat16 hz = __float2bfloat16_rn(v.z);
    __nv_bfloat16 hw = __float2bfloat16_rn(v.w);
    __nv_bfloat16 lx = __float2bfloat16_rn(v.x - __bfloat162float(hx));
    __nv_bfloat16 ly = __float2bfloat16_rn(v.y - __bfloat162float(hy));
    __nv_bfloat16 lz = __float2bfloat16_rn(v.z - __bfloat162float(hz));
    __nv_bfloat16 lw = __float2bfloat16_rn(v.w - __bfloat162float(hw));
    hi = (u64)__bfloat16_as_ushort(hx) | ((u64)__bfloat16_as_ushort(hy) << 16)
       | ((u64)__bfloat16_as_ushort(hz) << 32) | ((u64)__bfloat16_as_ushort(hw) << 48);
    lo = (u64)__bfloat16_as_ushort(lx) | ((u64)__bfloat16_as_ushort(ly) << 16)
       | ((u64)__bfloat16_as_ushort(lz) << 32) | ((u64)__bfloat16_as_ushort(lw) << 48);
}

#define MMA16816(c, a, b) \
    asm volatile( \
        "mma.sync.aligned.m16n8k16.row.col.f32.bf16.bf16.f32 " \
        "{%0,%1,%2,%3}, {%4,%5,%6,%7}, {%8,%9}, {%0,%1,%2,%3};" \
        : "+f"((c)[0]), "+f"((c)[1]), "+f"((c)[2]), "+f"((c)[3]) \
        : "r"((a)[0]), "r"((a)[1]), "r"((a)[2]), "r"((a)[3]), \
          "r"((b)[0]), "r"((b)[1]))

#define LDSM_X4(r0, r1, r2, r3, addr) \
    asm volatile("ldmatrix.sync.aligned.m8n8.x4.shared.b16 {%0,%1,%2,%3}, [%4];" \
                 : "=r"(r0), "=r"(r1), "=r"(r2), "=r"(r3) : "r"(addr))

// ---------------- weight prep: [n][k] bf16 hi/lo pitched images ---------------
template <int BN>
__global__ void k_prepW(const float* __restrict__ W, char* __restrict__ hi_img,
                        char* __restrict__ lo_img) {
    int i = blockIdx.x * blockDim.x + threadIdx.x;  // (n, k4)
    if (i >= BN * 32) return;
    int n = i >> 5;
    int k4 = (i & 31) * 4;
    float4 v;
    v.x = W[(size_t)(k4 + 0) * BN + n];
    v.y = W[(size_t)(k4 + 1) * BN + n];
    v.z = W[(size_t)(k4 + 2) * BN + n];
    v.w = W[(size_t)(k4 + 3) * BN + n];
    u64 hi, lo;
    split4(v, hi, lo);
    size_t off = (size_t)n * PITCHB + (size_t)k4 * 2;
    *reinterpret_cast<u64*>(hi_img + off) = hi;
    *reinterpret_cast<u64*>(lo_img + off) = lo;
}

// ---------------- mma.sync GEMM v4: BM=64, 2 CTA/SM, ldmatrix ----------------
// C[M,BN] = A[M,128] @ W[128,BN]; fused 3-term bf16 split in one K pass.
// 512 thr / 16 warps, warp tile 16 x (BN/4).
template <int BN>
__global__ __launch_bounds__(512, 2) void k_mma(const float* __restrict__ A,
                                                const char* __restrict__ BhiImg,
                                                const char* __restrict__ BloImg,
                                                float* __restrict__ C, int M) {
    extern __shared__ char smem[];
    constexpr int A_BYTES = 64 * PITCHB;      // 17408
    constexpr int B_BYTES = BN * PITCHB;
    char* sAhi = smem;
    char* sAlo = smem + A_BYTES;
    char* sBhi = smem + 2 * A_BYTES;
    char* sBlo = sBhi + B_BYTES;

    int tid = threadIdx.x;
    int blockRow = blockIdx.x * 64;

    // load + split A tile (64 rows x 128 cols fp32 -> hi/lo bf16)
    for (int i = tid; i < 64 * 32; i += 512) {
        int row = i >> 5;
        int c4 = (i & 31) * 4;
        float4 v = make_float4(0.f, 0.f, 0.f, 0.f);
        int grow = blockRow + row;
        if (grow < M)
            v = *reinterpret_cast<const float4*>(&A[(size_t)grow * 128 + c4]);
        u64 hi, lo;
        split4(v, hi, lo);
        size_t off = (size_t)row * PITCHB + (size_t)c4 * 2;
        *reinterpret_cast<u64*>(sAhi + off) = hi;
        *reinterpret_cast<u64*>(sAlo + off) = lo;
    }
    // raw-copy pre-split weight images (L2-resident)
    {
        const float4* sH = reinterpret_cast<const float4*>(BhiImg);
        const float4* sL = reinterpret_cast<const float4*>(BloImg);
        float4* dH = reinterpret_cast<float4*>(sBhi);
        float4* dL = reinterpret_cast<float4*>(sBlo);
        for (int i = tid; i < BN * 17; i += 512) {  // BN*272/16
            dH[i] = sH[i];
            dL[i] = sL[i];
        }
    }
    __syncthreads();

    int wid = tid >> 5, lane = tid & 31;
    int g = lane >> 2, t = lane & 3;
    constexpr int WN = BN / 4;        // 32 (BN=128) or 16 (BN=64)
    constexpr int NT = WN / 8;        // 4 or 2
    constexpr int NPAIR = NT / 2;     // 2 or 1
    int wm = wid & 3, wn = wid >> 2;
    int rowbase = wm * 16;
    int colbase = wn * WN;

    // ldmatrix lane addressing: row = lane%16, +16B column select for lane>=16
    u32 lrow = lane & 15;
    u32 lsel = (lane >> 4) << 4;
    u32 aHiB = smem_u32(sAhi) + (rowbase + lrow) * PITCHB + lsel;
    u32 aLoB = aHiB + A_BYTES;
    u32 bHiB[NPAIR], bLoB[NPAIR];
#pragma unroll
    for (int p = 0; p < NPAIR; p++) {
        bHiB[p] = smem_u32(sBhi) + (colbase + p * 16 + lrow) * PITCHB + lsel;
        bLoB[p] = bHiB[p] + B_BYTES;
    }

    float c[NT][4];
#pragma unroll
    for (int nt = 0; nt < NT; nt++)
#pragma unroll
        for (int j = 0; j < 4; j++) c[nt][j] = 0.f;

#pragma unroll
    for (int k0 = 0; k0 < 128; k0 += 16) {
        u32 koff = k0 * 2;
        u32 ah[4], al[4];
        LDSM_X4(ah[0], ah[1], ah[2], ah[3], aHiB + koff);
        LDSM_X4(al[0], al[1], al[2], al[3], aLoB + koff);
        u32 bh[NT][2], bl[NT][2];
#pragma unroll
        for (int p = 0; p < NPAIR; p++) {
            u32 r0, r1, r2, r3;
            LDSM_X4(r0, r1, r2, r3, bHiB[p] + koff);
            bh[2 * p + 0][0] = r0; bh[2 * p + 1][0] = r1;
            bh[2 * p + 0][1] = r2; bh[2 * p + 1][1] = r3;
            LDSM_X4(r0, r1, r2, r3, bLoB[p] + koff);
            bl[2 * p + 0][0] = r0; bl[2 * p + 1][0] = r1;
            bl[2 * p + 0][1] = r2; bl[2 * p + 1][1] = r3;
        }
        // 3 terms: hi*hi, hi*lo, lo*hi
#pragma unroll
        for (int nt = 0; nt < NT; nt++) MMA16816(c[nt], ah, bh[nt]);
#pragma unroll
        for (int nt = 0; nt < NT; nt++) MMA16816(c[nt], ah, bl[nt]);
#pragma unroll
        for (int nt = 0; nt < NT; nt++) MMA16816(c[nt], al, bh[nt]);
    }

    // epilogue: fragment-owner float2 stores (rows g and g+8 of warp tile)
    int row = blockRow + rowbase + g;
#pragma unroll
    for (int nt = 0; nt < NT; nt++) {
        int col = colbase + nt * 8 + 2 * t;
        if (row < M) {
            float2 o; o.x = c[nt][0]; o.y = c[nt][1];
            *reinterpret_cast<float2*>(&C[(size_t)row * BN + col]) = o;
        }
        if (row + 8 < M) {
            float2 o; o.x = c[nt][2]; o.y = c[nt][3];
            *reinterpret_cast<float2*>(&C[(size_t)(row + 8) * BN + col]) = o;
        }
    }
}

// ---------------- CSR build ---------------------------------------------------
__global__ void k_init(void) {
    int v = blockIdx.x * blockDim.x + threadIdx.x;
    if (v < NNODES) { g_deg[v] = 1; g_cursor[v] = 0; }
}
__global__ void k_count(const int* __restrict__ dst) {
    int e = blockIdx.x * blockDim.x + threadIdx.x;
    if (e < NEDGES) atomicAdd(&g_deg[dst[e]], 1);
}
__global__ void k_scan_block(void) {
    __shared__ int wsum[8];
    int tid = threadIdx.x;
    int base = blockIdx.x * SCAN_CHUNK + tid * 4;
    int v[4];
#pragma unroll
    for (int i = 0; i < 4; i++) {
        int idx = base + i;
        v[i] = (idx < NNODES) ? (g_deg[idx] - 1) : 0;
        if (idx < NNODES) g_dinv[idx] = rsqrtf((float)(v[i] + 1));
    }
    int e0 = 0, e1 = v[0], e2 = v[0] + v[1], e3 = v[0] + v[1] + v[2];
    int tot = e3 + v[3];
    int lane = tid & 31, wid = tid >> 5;
    int x = tot;
#pragma unroll
    for (int off = 1; off < 32; off <<= 1) {
        int y = __shfl_up_sync(0xFFFFFFFFu, x, off);
        if (lane >= off) x += y;
    }
    if (lane == 31) wsum[wid] = x;
    __syncthreads();
    if (wid == 0) {
        int tt = (lane < 8) ? wsum[lane] : 0;
        int xx = tt;
#pragma unroll
        for (int off = 1; off < 8; off <<= 1) {
            int y = __shfl_up_sync(0xFFFFFFFFu, xx, off);
            if (lane >= off) xx += y;
        }
        if (lane < 8) wsum[lane] = xx - tt;
    }
    __syncthreads();
    int texc = wsum[wid] + (x - tot);
    if (base + 0 < NNODES) g_off[base + 0] = texc + e0;
    if (base + 1 < NNODES) g_off[base + 1] = texc + e1;
    if (base + 2 < NNODES) g_off[base + 2] = texc + e2;
    if (base + 3 < NNODES) g_off[base + 3] = texc + e3;
    if (tid == blockDim.x - 1) g_bsum[blockIdx.x] = texc + tot;
}
__global__ void k_scan_top(void) {
    int acc = 0;
    for (int b = 0; b < SCAN_BLOCKS; b++) {
        int t = g_bsum[b];
        g_bsum[b] = acc;
        acc += t;
    }
}
__global__ void k_scan_add(void) {
    int tid = threadIdx.x;
    int base = blockIdx.x * SCAN_CHUNK + tid * 4;
    int add = g_bsum[blockIdx.x];
#pragma unroll
    for (int i = 0; i < 4; i++) {
        int idx = base + i;
        if (idx < NNODES) g_off[idx] += add;
    }
}
__global__ void k_scatter(const int* __restrict__ src, const int* __restrict__ dst) {
    int e = blockIdx.x * blockDim.x + threadIdx.x;
    if (e >= NEDGES) return;
    int s = src[e], d = dst[e];
    int pos = g_off[d] + atomicAdd(&g_cursor[d], 1);
    g_csr[pos] = make_int2(s, __float_as_int(g_dinv[s] * g_dinv[d]));
}

// ---------------- Aggregation -------------------------------------------------
template <int DIM, bool RELU>
__global__ __launch_bounds__(256) void k_agg(const float* __restrict__ h,
                                             const float* __restrict__ bias,
                                             float* __restrict__ out) {
    int warp = (blockIdx.x * blockDim.x + threadIdx.x) >> 5;
    if (warp >= NNODES) return;
    int lane = threadIdx.x & 31;

    float dv = g_dinv[warp];
    float wself = dv * dv;
    int beg = g_off[warp];
    int end = beg + (g_deg[warp] - 1);
    const int2* __restrict__ cp = g_csr;

    if (DIM == 128) {
        const float4* hp = reinterpret_cast<const float4*>(h);
        float4 sv = hp[(size_t)warp * 32 + lane];
        float ax = sv.x * wself, ay = sv.y * wself, az = sv.z * wself, aw = sv.w * wself;
        int e = beg;
        for (; e + 3 < end; e += 4) {
            int2 p0 = cp[e], p1 = cp[e + 1], p2 = cp[e + 2], p3 = cp[e + 3];
            float w0 = __int_as_float(p0.y), w1 = __int_as_float(p1.y);
            float w2 = __int_as_float(p2.y), w3 = __int_as_float(p3.y);
            float4 v0 = hp[(size_t)p0.x * 32 + lane];
            float4 v1 = hp[(size_t)p1.x * 32 + lane];
            float4 v2 = hp[(size_t)p2.x * 32 + lane];
            float4 v3 = hp[(size_t)p3.x * 32 + lane];
            ax += v0.x * w0 + v1.x * w1 + v2.x * w2 + v3.x * w3;
            ay += v0.y * w0 + v1.y * w1 + v2.y * w2 + v3.y * w3;
            az += v0.z * w0 + v1.z * w1 + v2.z * w2 + v3.z * w3;
            aw += v0.w * w0 + v1.w * w1 + v2.w * w2 + v3.w * w3;
        }
        for (; e < end; e++) {
            int2 p0 = cp[e];
            float w0 = __int_as_float(p0.y);
            float4 v0 = hp[(size_t)p0.x * 32 + lane];
            ax += v0.x * w0; ay += v0.y * w0; az += v0.z * w0; aw += v0.w * w0;
        }
        float4 b4 = reinterpret_cast<const float4*>(bias)[lane];
        ax += b4.x; ay += b4.y; az += b4.z; aw += b4.w;
        if (RELU) {
            ax = fmaxf(ax, 0.f); ay = fmaxf(ay, 0.f);
            az = fmaxf(az, 0.f); aw = fmaxf(aw, 0.f);
        }
        float4 o; o.x = ax; o.y = ay; o.z = az; o.w = aw;
        reinterpret_cast<float4*>(out)[(size_t)warp * 32 + lane] = o;
    } else {  // DIM == 64
        const float2* hp = reinterpret_cast<const float2*>(h);
        float2 sv = hp[(size_t)warp * 32 + lane];
        float ax = sv.x * wself, ay = sv.y * wself;
        int e = beg;
        for (; e + 3 < end; e += 4) {
            int2 p0 = cp[e], p1 = cp[e + 1], p2 = cp[e + 2], p3 = cp[e + 3];
            float w0 = __int_as_float(p0.y), w1 = __int_as_float(p1.y);
            float w2 = __int_as_float(p2.y), w3 = __int_as_float(p3.y);
            float2 v0 = hp[(size_t)p0.x * 32 + lane];
            float2 v1 = hp[(size_t)p1.x * 32 + lane];
            float2 v2 = hp[(size_t)p2.x * 32 + lane];
            float2 v3 = hp[(size_t)p3.x * 32 + lane];
            ax += v0.x * w0 + v1.x * w1 + v2.x * w2 + v3.x * w3;
            ay += v0.y * w0 + v1.y * w1 + v2.y * w2 + v3.y * w3;
        }
        for (; e < end; e++) {
            int2 p0 = cp[e];
            float w0 = __int_as_float(p0.y);
            float2 v0 = hp[(size_t)p0.x * 32 + lane];
            ax += v0.x * w0; ay += v0.y * w0;
        }
        float2 b2 = reinterpret_cast<const float2*>(bias)[lane];
        ax += b2.x; ay += b2.y;
        if (RELU) { ax = fmaxf(ax, 0.f); ay = fmaxf(ay, 0.f); }
        float2 o; o.x = ax; o.y = ay;
        reinterpret_cast<float2*>(out)[(size_t)warp * 32 + lane] = o;
    }
}

// ---------------- launch ------------------------------------------------------
extern "C" void kernel_launch(void* const* d_in, const int* in_sizes, int n_in,
                              void* d_out, int out_size) {
    const float* x  = (const float*)d_in[0];
    const int*   ei = (const int*)d_in[1];
    const float* W1 = (const float*)d_in[2];
    const float* b1 = (const float*)d_in[3];
    const float* W2 = (const float*)d_in[4];
    const float* b2 = (const float*)d_in[5];
    const float* W3 = (const float*)d_in[6];
    const float* b3 = (const float*)d_in[7];
    float* out = (float*)d_out;

    const int* src = ei;
    const int* dst = ei + NEDGES;

    float* bufA; cudaGetSymbolAddress((void**)&bufA, g_bufA);
    float* bufB; cudaGetSymbolAddress((void**)&bufB, g_bufB);
    char *w1h, *w1l, *w2h, *w2l, *w3h, *w3l;
    cudaGetSymbolAddress((void**)&w1h, g_W1hi); cudaGetSymbolAddress((void**)&w1l, g_W1lo);
    cudaGetSymbolAddress((void**)&w2h, g_W2hi); cudaGetSymbolAddress((void**)&w2l, g_W2lo);
    cudaGetSymbolAddress((void**)&w3h, g_W3hi); cudaGetSymbolAddress((void**)&w3l, g_W3lo);

    const int SMEM128 = 2 * 64 * PITCHB + 2 * 128 * PITCHB;  // 104448
    const int SMEM64  = 2 * 64 * PITCHB + 2 * 64 * PITCHB;   //  69632
    cudaFuncSetAttribute(k_mma<128>, cudaFuncAttributeMaxDynamicSharedMemorySize, SMEM128);
    cudaFuncSetAttribute(k_mma<64>,  cudaFuncAttributeMaxDynamicSharedMemorySize, SMEM64);

    const int TB = 256;
    int nodeBlocks = (NNODES + TB - 1) / TB;
    int edgeBlocks = (NEDGES + TB - 1) / TB;
    int gemmBlocks = (NNODES + 63) / 64;     // 1563
    int aggBlocks  = (NNODES + 7) / 8;

    // k_mma<128> is the 4th launch -> the ncu-profiled launch
    k_prepW<128><<<16, TB>>>(W1, w1h, w1l);
    k_init<<<nodeBlocks, TB>>>();
    k_count<<<edgeBlocks, TB>>>(dst);
    k_mma<128><<<gemmBlocks, 512, SMEM128>>>(x, w1h, w1l, bufA, NNODES);  // 4th (profiled)
    k_scan_block<<<SCAN_BLOCKS, TB>>>();
    k_scan_top<<<1, 1>>>();
    k_scan_add<<<SCAN_BLOCKS, TB>>>();
    k_scatter<<<edgeBlocks, TB>>>(src, dst);
    k_prepW<128><<<16, TB>>>(W2, w2h, w2l);
    k_prepW<64><<<8, TB>>>(W3, w3h, w3l);

    k_agg<128, true><<<aggBlocks, TB>>>(bufA, b1, bufB);
    k_mma<128><<<gemmBlocks, 512, SMEM128>>>(bufB, w2h, w2l, bufA, NNODES);
    k_agg<128, true><<<aggBlocks, TB>>>(bufA, b2, bufB);
    k_mma<64><<<gemmBlocks, 512, SMEM64>>>(bufB, w3h, w3l, bufA, NNODES);
    k_agg<64, false><<<aggBlocks, TB>>>(bufA, b3, out);
}